// round 1
// baseline (speedup 1.0000x reference)
#include <cuda_runtime.h>
#include <math.h>

#define NH 16
#define NB 2
#define NS 2048
#define DM 1024
#define DK 64
#define NROWS (NS*NB)   // 4096

// Scratch (allocation-free rule: __device__ globals)
__device__ __align__(16) float g_Q[NH*NB*NS*DK];
__device__ __align__(16) float g_K[NH*NB*NS*DK];
__device__ __align__(16) float g_V[NH*NB*NS*DK];
__device__ __align__(16) float g_ctx[(size_t)NROWS*DM];

// ---------------------------------------------------------------------------
// NT GEMM: out = X[NROWS,DM] @ W[DM,DM]^T + bias
// mode 0: scatter into [h, b, s, dk] layout (fused reshape/transpose)
// mode 1: plain row-major [NROWS, DM]
// 64x64 output tile, K-step 16, 256 threads, 4x4 microtile per thread.
// ---------------------------------------------------------------------------
__global__ void gemm_nt_kernel(const float* __restrict__ X,
                               const float* __restrict__ W,
                               const float* __restrict__ bias,
                               float* __restrict__ out, int mode)
{
    __shared__ __align__(16) float Xs[16][68];
    __shared__ __align__(16) float Ws[16][68];

    const int tid = threadIdx.x;            // 0..255
    const int ty  = tid >> 4;               // 0..15 -> rows
    const int tx  = tid & 15;               // 0..15 -> cols
    const int rT  = blockIdx.y << 6;
    const int cT  = blockIdx.x << 6;

    const int lr = tid >> 2;                // 0..63 (tile row for loading)
    const int lk = (tid & 3) << 2;          // 0,4,8,12 (k offset)

    const float* xrow = X + (size_t)(rT + lr) * DM + lk;
    const float* wrow = W + (size_t)(cT + lr) * DM + lk;

    float acc[4][4] = {};

    for (int kk = 0; kk < DM; kk += 16) {
        float4 xv = *(const float4*)(xrow + kk);
        float4 wv = *(const float4*)(wrow + kk);
        Xs[lk+0][lr] = xv.x; Xs[lk+1][lr] = xv.y;
        Xs[lk+2][lr] = xv.z; Xs[lk+3][lr] = xv.w;
        Ws[lk+0][lr] = wv.x; Ws[lk+1][lr] = wv.y;
        Ws[lk+2][lr] = wv.z; Ws[lk+3][lr] = wv.w;
        __syncthreads();

        #pragma unroll
        for (int k = 0; k < 16; k++) {
            float a[4], b[4];
            *(float4*)a = *(const float4*)&Xs[k][ty << 2];
            *(float4*)b = *(const float4*)&Ws[k][tx << 2];
            #pragma unroll
            for (int i = 0; i < 4; i++)
                #pragma unroll
                for (int j = 0; j < 4; j++)
                    acc[i][j] = fmaf(a[i], b[j], acc[i][j]);
        }
        __syncthreads();
    }

    #pragma unroll
    for (int i = 0; i < 4; i++) {
        const int r = rT + (ty << 2) + i;
        #pragma unroll
        for (int j = 0; j < 4; j++) {
            const int c = cT + (tx << 2) + j;
            const float v = acc[i][j] + bias[c];
            if (mode == 0) {
                // X row r corresponds to (s, b) with r = s*NB + b
                const int s = r >> 1, b = r & 1;
                const int h = c >> 6, dk = c & 63;
                out[(((size_t)(h * NB + b) * NS + s) << 6) + dk] = v;
            } else {
                out[(size_t)r * DM + c] = v;
            }
        }
    }
}

// ---------------------------------------------------------------------------
// Flash attention, fp32. One block = one (head,batch) x 32 query rows.
// Streams over 64-key tiles with online softmax. 128 threads.
// Thread microtile: 4 q-rows x 4 cols (cols = key idx for S, dk for O).
// Writes context in [s, b, h*64+dk] layout (input to output projection).
// ---------------------------------------------------------------------------
__global__ void attn_kernel(const float* __restrict__ Qg_,
                            const float* __restrict__ Kg_,
                            const float* __restrict__ Vg_,
                            float* __restrict__ ctx)
{
    __shared__ __align__(16) float Qs[64 * 36];  // [d][qr], qr<32
    __shared__ __align__(16) float kv[64 * 68];  // Ks: [d][kc] ; Vs: [kc][d]
    __shared__ __align__(16) float Ps[64 * 36];  // [kc][qr]

    const int tid = threadIdx.x;     // 0..127
    const int ty  = tid >> 4;        // 0..7  -> q rows (ty*4+i)
    const int tx  = tid & 15;        // 0..15 -> cols   (tx*4+j)
    const int qt  = blockIdx.x;      // query tile (32 rows)
    const int hb  = blockIdx.y;      // h*NB + b

    const float* Qg = Qg_ + ((size_t)hb * NS << 6);
    const float* Kg = Kg_ + ((size_t)hb * NS << 6);
    const float* Vg = Vg_ + ((size_t)hb * NS << 6);

    // Load Q tile transposed: Qs[d][qr]
    #pragma unroll
    for (int it = 0; it < 4; it++) {
        const int e  = it * 512 + tid * 4;   // < 2048
        const int qr = e >> 6, d = e & 63;
        float4 q4 = *(const float4*)&Qg[((size_t)(qt * 32 + qr) << 6) + d];
        Qs[(d+0)*36 + qr] = q4.x; Qs[(d+1)*36 + qr] = q4.y;
        Qs[(d+2)*36 + qr] = q4.z; Qs[(d+3)*36 + qr] = q4.w;
    }

    float m[4], l[4], acc[4][4];
    #pragma unroll
    for (int i = 0; i < 4; i++) {
        m[i] = -1e30f; l[i] = 0.f;
        #pragma unroll
        for (int j = 0; j < 4; j++) acc[i][j] = 0.f;
    }

    for (int kt = 0; kt < NS / 64; kt++) {
        __syncthreads();   // prev-iter PV reads of kv/Ps complete; Qs visible (iter 0)
        // Load K tile transposed: kv[d][kc]
        #pragma unroll
        for (int it = 0; it < 8; it++) {
            const int e  = it * 512 + tid * 4;   // < 4096
            const int kc = e >> 6, d = e & 63;
            float4 k4 = *(const float4*)&Kg[((size_t)(kt * 64 + kc) << 6) + d];
            kv[(d+0)*68 + kc] = k4.x; kv[(d+1)*68 + kc] = k4.y;
            kv[(d+2)*68 + kc] = k4.z; kv[(d+3)*68 + kc] = k4.w;
        }
        __syncthreads();

        // S = (Q K^T) / 8 for this tile -> sacc[4][4]
        float sacc[4][4] = {};
        #pragma unroll 4
        for (int d = 0; d < 64; d++) {
            float a[4], b[4];
            *(float4*)a = *(const float4*)&Qs[d*36 + (ty << 2)];
            *(float4*)b = *(const float4*)&kv[d*68 + (tx << 2)];
            #pragma unroll
            for (int i = 0; i < 4; i++)
                #pragma unroll
                for (int j = 0; j < 4; j++)
                    sacc[i][j] = fmaf(a[i], b[j], sacc[i][j]);
        }

        // Online softmax update (per q-row, shuffled across the 16 tx lanes)
        #pragma unroll
        for (int i = 0; i < 4; i++) {
            float tm = -1e30f;
            #pragma unroll
            for (int j = 0; j < 4; j++) {
                sacc[i][j] *= 0.125f;                // 1/sqrt(64)
                tm = fmaxf(tm, sacc[i][j]);
            }
            #pragma unroll
            for (int off = 8; off; off >>= 1)
                tm = fmaxf(tm, __shfl_xor_sync(0xffffffffu, tm, off));
            const float mn = fmaxf(m[i], tm);
            const float corr = __expf(m[i] - mn);
            float ls = 0.f;
            #pragma unroll
            for (int j = 0; j < 4; j++) {
                const float p = __expf(sacc[i][j] - mn);
                sacc[i][j] = p;
                ls += p;
            }
            #pragma unroll
            for (int off = 8; off; off >>= 1)
                ls += __shfl_xor_sync(0xffffffffu, ls, off);
            l[i] = l[i] * corr + ls;
            m[i] = mn;
            #pragma unroll
            for (int j = 0; j < 4; j++) acc[i][j] *= corr;
        }

        __syncthreads();   // everyone done reading kv (K) before V overwrites it

        // Store P transposed: Ps[kc][qr]; load V tile natural: kv[kc][d]
        #pragma unroll
        for (int i = 0; i < 4; i++)
            #pragma unroll
            for (int j = 0; j < 4; j++)
                Ps[((tx << 2) + j) * 36 + (ty << 2) + i] = sacc[i][j];
        #pragma unroll
        for (int it = 0; it < 8; it++) {
            const int e  = it * 512 + tid * 4;
            const int kc = e >> 6, d = e & 63;
            float4 v4 = *(const float4*)&Vg[((size_t)(kt * 64 + kc) << 6) + d];
            *(float4*)&kv[kc*68 + d] = v4;
        }
        __syncthreads();

        // O += P @ V
        #pragma unroll 4
        for (int kc = 0; kc < 64; kc++) {
            float a[4], b[4];
            *(float4*)a = *(const float4*)&Ps[kc*36 + (ty << 2)];
            *(float4*)b = *(const float4*)&kv[kc*68 + (tx << 2)];
            #pragma unroll
            for (int i = 0; i < 4; i++)
                #pragma unroll
                for (int j = 0; j < 4; j++)
                    acc[i][j] = fmaf(a[i], b[j], acc[i][j]);
        }
    }

    // Epilogue: O / l -> ctx[s, b, h*64+dk]
    const int h = hb >> 1, b = hb & 1;
    #pragma unroll
    for (int i = 0; i < 4; i++) {
        const float inv = 1.f / l[i];
        const int s = qt * 32 + (ty << 2) + i;
        #pragma unroll
        for (int j = 0; j < 4; j++) {
            const int c = (h << 6) + (tx << 2) + j;
            ctx[(size_t)(s * NB + b) * DM + c] = acc[i][j] * inv;
        }
    }
}

// ---------------------------------------------------------------------------
extern "C" void kernel_launch(void* const* d_in, const int* in_sizes, int n_in,
                              void* d_out, int out_size)
{
    const float* query = (const float*)d_in[0];
    const float* key_  = (const float*)d_in[1];
    const float* value = (const float*)d_in[2];
    const float* Wq = (const float*)d_in[3];
    const float* bq = (const float*)d_in[4];
    const float* Wk = (const float*)d_in[5];
    const float* bk = (const float*)d_in[6];
    const float* Wv = (const float*)d_in[7];
    const float* bv = (const float*)d_in[8];
    const float* Wo = (const float*)d_in[9];
    const float* bo = (const float*)d_in[10];
    float* out = (float*)d_out;

    float *pQ, *pK, *pV, *pC;
    cudaGetSymbolAddress((void**)&pQ, g_Q);
    cudaGetSymbolAddress((void**)&pK, g_K);
    cudaGetSymbolAddress((void**)&pV, g_V);
    cudaGetSymbolAddress((void**)&pC, g_ctx);

    dim3 gg(DM / 64, NROWS / 64);   // 16 x 64
    gemm_nt_kernel<<<gg, 256>>>(query, Wq, bq, pQ, 0);
    gemm_nt_kernel<<<gg, 256>>>(key_,  Wk, bk, pK, 0);
    gemm_nt_kernel<<<gg, 256>>>(value, Wv, bv, pV, 0);

    attn_kernel<<<dim3(NS / 32, NH * NB), 128>>>(pQ, pK, pV, pC);

    gemm_nt_kernel<<<gg, 256>>>(pC, Wo, bo, out, 1);
}

// round 3
// speedup vs baseline: 1.4339x; 1.4339x over previous
#include <cuda_runtime.h>
#include <cstdint>
#include <math.h>

#define NH 16
#define NB 2
#define NS 2048
#define DM 1024
#define DK 64
#define NROWS (NS*NB)   // 4096

// Scratch (allocation-free rule: __device__ globals)
__device__ __align__(16) float g_Q[NH*NB*NS*DK];
__device__ __align__(16) float g_K[NH*NB*NS*DK];
__device__ __align__(16) float g_V[NH*NB*NS*DK];
__device__ __align__(16) float g_ctx[(size_t)NROWS*DM];

// ---------------------------------------------------------------------------
// tf32 helpers (portable mma.sync path — compute_103 has no tcgen05)
// ---------------------------------------------------------------------------
__device__ __forceinline__ uint32_t f2tf32(float f) {
    uint32_t o;
    asm("cvt.rna.tf32.f32 %0, %1;" : "=r"(o) : "f"(f));
    return o;
}

__device__ __forceinline__ void mma_tf32(float c[4], const uint32_t a[4], const uint32_t b[2]) {
    asm volatile(
        "mma.sync.aligned.m16n8k8.row.col.f32.tf32.tf32.f32 "
        "{%0,%1,%2,%3}, {%4,%5,%6,%7}, {%8,%9}, {%0,%1,%2,%3};"
        : "+f"(c[0]), "+f"(c[1]), "+f"(c[2]), "+f"(c[3])
        : "r"(a[0]), "r"(a[1]), "r"(a[2]), "r"(a[3]), "r"(b[0]), "r"(b[1]));
}

// ---------------------------------------------------------------------------
// tf32 mma.sync NT GEMM: out = X[NROWS,DM] @ W[DM,DM]^T + bias
// CTA tile 128x128, K-chunk 16, 256 threads = 8 warps (2x4), warp tile 64x32.
// mode 0: scatter into [h, b, s, dk] layout; mode 1: row-major [NROWS, DM]
// ---------------------------------------------------------------------------
#define BM 128
#define BN 128
#define BK 16
#define LDS_STRIDE 20   // 16 + 4 pad (80B row stride, 16B-aligned)

__global__ __launch_bounds__(256, 2)
void gemm_mma_kernel(const float* __restrict__ X, const float* __restrict__ W,
                     const float* __restrict__ bias, float* __restrict__ out, int mode)
{
    __shared__ __align__(16) uint32_t As[2][BM * LDS_STRIDE];
    __shared__ __align__(16) uint32_t Bs[2][BN * LDS_STRIDE];

    const int tid = threadIdx.x;
    const int wid = tid >> 5, lid = tid & 31;
    const int wm  = wid >> 2;          // 0..1 -> 64-row slab
    const int wn  = wid & 3;           // 0..3 -> 32-col slab
    const int g   = lid >> 2;          // group id (0..7)
    const int t   = lid & 3;           // thread-in-group (0..3)

    const int rT = blockIdx.y << 7;
    const int cT = blockIdx.x << 7;

    // gmem load coords: 2 float4 per thread per tile (128x16 elems / 256 thr)
    const int lr0 = (tid * 4) >> 4;          // rows 0..63   (it=0)
    const int lr1 = lr0 + 64;                // rows 64..127 (it=1)
    const int lc  = (tid * 4) & 15;          // k offset 0,4,8,12

    float acc[4][4][4] = {};                 // [mt][nt][frag]
    float4 ra0, ra1, rb0, rb1;

    // prefetch chunk 0
    ra0 = *(const float4*)&X[(size_t)(rT + lr0) * DM + lc];
    ra1 = *(const float4*)&X[(size_t)(rT + lr1) * DM + lc];
    rb0 = *(const float4*)&W[(size_t)(cT + lr0) * DM + lc];
    rb1 = *(const float4*)&W[(size_t)(cT + lr1) * DM + lc];
    {
        uint4 u;
        u.x = f2tf32(ra0.x); u.y = f2tf32(ra0.y); u.z = f2tf32(ra0.z); u.w = f2tf32(ra0.w);
        *(uint4*)&As[0][lr0 * LDS_STRIDE + lc] = u;
        u.x = f2tf32(ra1.x); u.y = f2tf32(ra1.y); u.z = f2tf32(ra1.z); u.w = f2tf32(ra1.w);
        *(uint4*)&As[0][lr1 * LDS_STRIDE + lc] = u;
        u.x = f2tf32(rb0.x); u.y = f2tf32(rb0.y); u.z = f2tf32(rb0.z); u.w = f2tf32(rb0.w);
        *(uint4*)&Bs[0][lr0 * LDS_STRIDE + lc] = u;
        u.x = f2tf32(rb1.x); u.y = f2tf32(rb1.y); u.z = f2tf32(rb1.z); u.w = f2tf32(rb1.w);
        *(uint4*)&Bs[0][lr1 * LDS_STRIDE + lc] = u;
    }

    const int NCHUNK = DM / BK;   // 64
    for (int c = 0; c < NCHUNK; c++) {
        const int p = c & 1;
        __syncthreads();

        if (c + 1 < NCHUNK) {
            const int kk = (c + 1) << 4;
            ra0 = *(const float4*)&X[(size_t)(rT + lr0) * DM + kk + lc];
            ra1 = *(const float4*)&X[(size_t)(rT + lr1) * DM + kk + lc];
            rb0 = *(const float4*)&W[(size_t)(cT + lr0) * DM + kk + lc];
            rb1 = *(const float4*)&W[(size_t)(cT + lr1) * DM + kk + lc];
        }

        #pragma unroll
        for (int ks = 0; ks < BK; ks += 8) {
            uint32_t a[4][4], b[4][2];
            #pragma unroll
            for (int mt = 0; mt < 4; mt++) {
                const int row = wm * 64 + mt * 16 + g;
                a[mt][0] = As[p][row * LDS_STRIDE + ks + t];
                a[mt][1] = As[p][(row + 8) * LDS_STRIDE + ks + t];
                a[mt][2] = As[p][row * LDS_STRIDE + ks + t + 4];
                a[mt][3] = As[p][(row + 8) * LDS_STRIDE + ks + t + 4];
            }
            #pragma unroll
            for (int nt = 0; nt < 4; nt++) {
                const int col = wn * 32 + nt * 8 + g;
                b[nt][0] = Bs[p][col * LDS_STRIDE + ks + t];
                b[nt][1] = Bs[p][col * LDS_STRIDE + ks + t + 4];
            }
            #pragma unroll
            for (int mt = 0; mt < 4; mt++)
                #pragma unroll
                for (int nt = 0; nt < 4; nt++)
                    mma_tf32(acc[mt][nt], a[mt], b[nt]);
        }

        if (c + 1 < NCHUNK) {
            const int q = (c + 1) & 1;
            uint4 u;
            u.x = f2tf32(ra0.x); u.y = f2tf32(ra0.y); u.z = f2tf32(ra0.z); u.w = f2tf32(ra0.w);
            *(uint4*)&As[q][lr0 * LDS_STRIDE + lc] = u;
            u.x = f2tf32(ra1.x); u.y = f2tf32(ra1.y); u.z = f2tf32(ra1.z); u.w = f2tf32(ra1.w);
            *(uint4*)&As[q][lr1 * LDS_STRIDE + lc] = u;
            u.x = f2tf32(rb0.x); u.y = f2tf32(rb0.y); u.z = f2tf32(rb0.z); u.w = f2tf32(rb0.w);
            *(uint4*)&Bs[q][lr0 * LDS_STRIDE + lc] = u;
            u.x = f2tf32(rb1.x); u.y = f2tf32(rb1.y); u.z = f2tf32(rb1.z); u.w = f2tf32(rb1.w);
            *(uint4*)&Bs[q][lr1 * LDS_STRIDE + lc] = u;
        }
    }

    // Epilogue: c0:(row g, col 2t) c1:(g, 2t+1) c2:(g+8, 2t) c3:(g+8, 2t+1)
    #pragma unroll
    for (int mt = 0; mt < 4; mt++) {
        #pragma unroll
        for (int nt = 0; nt < 4; nt++) {
            const int col = cT + wn * 32 + nt * 8 + 2 * t;
            const float bx = bias[col], by = bias[col + 1];
            #pragma unroll
            for (int half = 0; half < 2; half++) {
                const int row = rT + wm * 64 + mt * 16 + g + half * 8;
                float2 o;
                o.x = acc[mt][nt][half * 2 + 0] + bx;
                o.y = acc[mt][nt][half * 2 + 1] + by;
                if (mode == 0) {
                    const int h = col >> 6, dk = col & 63;
                    const int s = row >> 1, b = row & 1;
                    *(float2*)&out[(((size_t)(h * NB + b) * NS + s) << 6) + dk] = o;
                } else {
                    *(float2*)&out[(size_t)row * DM + col] = o;
                }
            }
        }
    }
}

// ---------------------------------------------------------------------------
// Flash attention, fp32 SIMT (unchanged; R3 target for mma.sync).
// ---------------------------------------------------------------------------
__global__ void attn_kernel(const float* __restrict__ Qg_,
                            const float* __restrict__ Kg_,
                            const float* __restrict__ Vg_,
                            float* __restrict__ ctx)
{
    __shared__ __align__(16) float Qs[64 * 36];
    __shared__ __align__(16) float kv[64 * 68];
    __shared__ __align__(16) float Ps[64 * 36];

    const int tid = threadIdx.x;
    const int ty  = tid >> 4;
    const int tx  = tid & 15;
    const int qt  = blockIdx.x;
    const int hb  = blockIdx.y;

    const float* Qg = Qg_ + ((size_t)hb * NS << 6);
    const float* Kg = Kg_ + ((size_t)hb * NS << 6);
    const float* Vg = Vg_ + ((size_t)hb * NS << 6);

    #pragma unroll
    for (int it = 0; it < 4; it++) {
        const int e  = it * 512 + tid * 4;
        const int qr = e >> 6, d = e & 63;
        float4 q4 = *(const float4*)&Qg[((size_t)(qt * 32 + qr) << 6) + d];
        Qs[(d+0)*36 + qr] = q4.x; Qs[(d+1)*36 + qr] = q4.y;
        Qs[(d+2)*36 + qr] = q4.z; Qs[(d+3)*36 + qr] = q4.w;
    }

    float m[4], l[4], acc[4][4];
    #pragma unroll
    for (int i = 0; i < 4; i++) {
        m[i] = -1e30f; l[i] = 0.f;
        #pragma unroll
        for (int j = 0; j < 4; j++) acc[i][j] = 0.f;
    }

    for (int kt = 0; kt < NS / 64; kt++) {
        __syncthreads();
        #pragma unroll
        for (int it = 0; it < 8; it++) {
            const int e  = it * 512 + tid * 4;
            const int kc = e >> 6, d = e & 63;
            float4 k4 = *(const float4*)&Kg[((size_t)(kt * 64 + kc) << 6) + d];
            kv[(d+0)*68 + kc] = k4.x; kv[(d+1)*68 + kc] = k4.y;
            kv[(d+2)*68 + kc] = k4.z; kv[(d+3)*68 + kc] = k4.w;
        }
        __syncthreads();

        float sacc[4][4] = {};
        #pragma unroll 4
        for (int d = 0; d < 64; d++) {
            float a[4], b[4];
            *(float4*)a = *(const float4*)&Qs[d*36 + (ty << 2)];
            *(float4*)b = *(const float4*)&kv[d*68 + (tx << 2)];
            #pragma unroll
            for (int i = 0; i < 4; i++)
                #pragma unroll
                for (int j = 0; j < 4; j++)
                    sacc[i][j] = fmaf(a[i], b[j], sacc[i][j]);
        }

        #pragma unroll
        for (int i = 0; i < 4; i++) {
            float tm = -1e30f;
            #pragma unroll
            for (int j = 0; j < 4; j++) {
                sacc[i][j] *= 0.125f;
                tm = fmaxf(tm, sacc[i][j]);
            }
            #pragma unroll
            for (int off = 8; off; off >>= 1)
                tm = fmaxf(tm, __shfl_xor_sync(0xffffffffu, tm, off));
            const float mn = fmaxf(m[i], tm);
            const float corr = __expf(m[i] - mn);
            float ls = 0.f;
            #pragma unroll
            for (int j = 0; j < 4; j++) {
                const float p = __expf(sacc[i][j] - mn);
                sacc[i][j] = p;
                ls += p;
            }
            #pragma unroll
            for (int off = 8; off; off >>= 1)
                ls += __shfl_xor_sync(0xffffffffu, ls, off);
            l[i] = l[i] * corr + ls;
            m[i] = mn;
            #pragma unroll
            for (int j = 0; j < 4; j++) acc[i][j] *= corr;
        }

        __syncthreads();

        #pragma unroll
        for (int i = 0; i < 4; i++)
            #pragma unroll
            for (int j = 0; j < 4; j++)
                Ps[((tx << 2) + j) * 36 + (ty << 2) + i] = sacc[i][j];
        #pragma unroll
        for (int it = 0; it < 8; it++) {
            const int e  = it * 512 + tid * 4;
            const int kc = e >> 6, d = e & 63;
            float4 v4 = *(const float4*)&Vg[((size_t)(kt * 64 + kc) << 6) + d];
            *(float4*)&kv[kc*68 + d] = v4;
        }
        __syncthreads();

        #pragma unroll 4
        for (int kc = 0; kc < 64; kc++) {
            float a[4], b[4];
            *(float4*)a = *(const float4*)&Ps[kc*36 + (ty << 2)];
            *(float4*)b = *(const float4*)&kv[kc*68 + (tx << 2)];
            #pragma unroll
            for (int i = 0; i < 4; i++)
                #pragma unroll
                for (int j = 0; j < 4; j++)
                    acc[i][j] = fmaf(a[i], b[j], acc[i][j]);
        }
    }

    const int h = hb >> 1, b = hb & 1;
    #pragma unroll
    for (int i = 0; i < 4; i++) {
        const float inv = 1.f / l[i];
        const int s = qt * 32 + (ty << 2) + i;
        #pragma unroll
        for (int j = 0; j < 4; j++) {
            const int c = (h << 6) + (tx << 2) + j;
            ctx[(size_t)(s * NB + b) * DM + c] = acc[i][j] * inv;
        }
    }
}

// ---------------------------------------------------------------------------
extern "C" void kernel_launch(void* const* d_in, const int* in_sizes, int n_in,
                              void* d_out, int out_size)
{
    const float* query = (const float*)d_in[0];
    const float* key_  = (const float*)d_in[1];
    const float* value = (const float*)d_in[2];
    const float* Wq = (const float*)d_in[3];
    const float* bq = (const float*)d_in[4];
    const float* Wk = (const float*)d_in[5];
    const float* bk = (const float*)d_in[6];
    const float* Wv = (const float*)d_in[7];
    const float* bv = (const float*)d_in[8];
    const float* Wo = (const float*)d_in[9];
    const float* bo = (const float*)d_in[10];
    float* out = (float*)d_out;

    float *pQ, *pK, *pV, *pC;
    cudaGetSymbolAddress((void**)&pQ, g_Q);
    cudaGetSymbolAddress((void**)&pK, g_K);
    cudaGetSymbolAddress((void**)&pV, g_V);
    cudaGetSymbolAddress((void**)&pC, g_ctx);

    dim3 gg(DM / BN, NROWS / BM);   // 8 x 32 = 256 CTAs
    gemm_mma_kernel<<<gg, 256>>>(query, Wq, bq, pQ, 0);
    gemm_mma_kernel<<<gg, 256>>>(key_,  Wk, bk, pK, 0);
    gemm_mma_kernel<<<gg, 256>>>(value, Wv, bv, pV, 0);

    attn_kernel<<<dim3(NS / 32, NH * NB), 128>>>(pQ, pK, pV, pC);

    gemm_mma_kernel<<<gg, 256>>>(pC, Wo, bo, out, 1);
}

// round 4
// speedup vs baseline: 3.0881x; 2.1536x over previous
#include <cuda_runtime.h>
#include <cstdint>
#include <math.h>

#define NH 16
#define NB 2
#define NS 2048
#define DM 1024
#define DK 64
#define NROWS (NS*NB)   // 4096

// Scratch (allocation-free rule: __device__ globals)
__device__ __align__(16) float g_Q[NH*NB*NS*DK];
__device__ __align__(16) float g_K[NH*NB*NS*DK];
__device__ __align__(16) float g_V[NH*NB*NS*DK];
__device__ __align__(16) float g_ctx[(size_t)NROWS*DM];

// ---------------------------------------------------------------------------
// tf32 helpers (portable mma.sync path — compute_103 has no tcgen05)
// ---------------------------------------------------------------------------
__device__ __forceinline__ uint32_t f2tf32(float f) {
    uint32_t o;
    asm("cvt.rna.tf32.f32 %0, %1;" : "=r"(o) : "f"(f));
    return o;
}

__device__ __forceinline__ void mma_tf32(float c[4], const uint32_t a[4], const uint32_t b[2]) {
    asm volatile(
        "mma.sync.aligned.m16n8k8.row.col.f32.tf32.tf32.f32 "
        "{%0,%1,%2,%3}, {%4,%5,%6,%7}, {%8,%9}, {%0,%1,%2,%3};"
        : "+f"(c[0]), "+f"(c[1]), "+f"(c[2]), "+f"(c[3])
        : "r"(a[0]), "r"(a[1]), "r"(a[2]), "r"(a[3]), "r"(b[0]), "r"(b[1]));
}

// ---------------------------------------------------------------------------
// tf32 mma.sync NT GEMM (unchanged from R3)
// ---------------------------------------------------------------------------
#define BM 128
#define BN 128
#define BK 16
#define LDS_STRIDE 20

__global__ __launch_bounds__(256, 2)
void gemm_mma_kernel(const float* __restrict__ X, const float* __restrict__ W,
                     const float* __restrict__ bias, float* __restrict__ out, int mode)
{
    __shared__ __align__(16) uint32_t As[2][BM * LDS_STRIDE];
    __shared__ __align__(16) uint32_t Bs[2][BN * LDS_STRIDE];

    const int tid = threadIdx.x;
    const int wid = tid >> 5, lid = tid & 31;
    const int wm  = wid >> 2;
    const int wn  = wid & 3;
    const int g   = lid >> 2;
    const int t   = lid & 3;

    const int rT = blockIdx.y << 7;
    const int cT = blockIdx.x << 7;

    const int lr0 = (tid * 4) >> 4;
    const int lr1 = lr0 + 64;
    const int lc  = (tid * 4) & 15;

    float acc[4][4][4] = {};
    float4 ra0, ra1, rb0, rb1;

    ra0 = *(const float4*)&X[(size_t)(rT + lr0) * DM + lc];
    ra1 = *(const float4*)&X[(size_t)(rT + lr1) * DM + lc];
    rb0 = *(const float4*)&W[(size_t)(cT + lr0) * DM + lc];
    rb1 = *(const float4*)&W[(size_t)(cT + lr1) * DM + lc];
    {
        uint4 u;
        u.x = f2tf32(ra0.x); u.y = f2tf32(ra0.y); u.z = f2tf32(ra0.z); u.w = f2tf32(ra0.w);
        *(uint4*)&As[0][lr0 * LDS_STRIDE + lc] = u;
        u.x = f2tf32(ra1.x); u.y = f2tf32(ra1.y); u.z = f2tf32(ra1.z); u.w = f2tf32(ra1.w);
        *(uint4*)&As[0][lr1 * LDS_STRIDE + lc] = u;
        u.x = f2tf32(rb0.x); u.y = f2tf32(rb0.y); u.z = f2tf32(rb0.z); u.w = f2tf32(rb0.w);
        *(uint4*)&Bs[0][lr0 * LDS_STRIDE + lc] = u;
        u.x = f2tf32(rb1.x); u.y = f2tf32(rb1.y); u.z = f2tf32(rb1.z); u.w = f2tf32(rb1.w);
        *(uint4*)&Bs[0][lr1 * LDS_STRIDE + lc] = u;
    }

    const int NCHUNK = DM / BK;
    for (int c = 0; c < NCHUNK; c++) {
        const int p = c & 1;
        __syncthreads();

        if (c + 1 < NCHUNK) {
            const int kk = (c + 1) << 4;
            ra0 = *(const float4*)&X[(size_t)(rT + lr0) * DM + kk + lc];
            ra1 = *(const float4*)&X[(size_t)(rT + lr1) * DM + kk + lc];
            rb0 = *(const float4*)&W[(size_t)(cT + lr0) * DM + kk + lc];
            rb1 = *(const float4*)&W[(size_t)(cT + lr1) * DM + kk + lc];
        }

        #pragma unroll
        for (int ks = 0; ks < BK; ks += 8) {
            uint32_t a[4][4], b[4][2];
            #pragma unroll
            for (int mt = 0; mt < 4; mt++) {
                const int row = wm * 64 + mt * 16 + g;
                a[mt][0] = As[p][row * LDS_STRIDE + ks + t];
                a[mt][1] = As[p][(row + 8) * LDS_STRIDE + ks + t];
                a[mt][2] = As[p][row * LDS_STRIDE + ks + t + 4];
                a[mt][3] = As[p][(row + 8) * LDS_STRIDE + ks + t + 4];
            }
            #pragma unroll
            for (int nt = 0; nt < 4; nt++) {
                const int col = wn * 32 + nt * 8 + g;
                b[nt][0] = Bs[p][col * LDS_STRIDE + ks + t];
                b[nt][1] = Bs[p][col * LDS_STRIDE + ks + t + 4];
            }
            #pragma unroll
            for (int mt = 0; mt < 4; mt++)
                #pragma unroll
                for (int nt = 0; nt < 4; nt++)
                    mma_tf32(acc[mt][nt], a[mt], b[nt]);
        }

        if (c + 1 < NCHUNK) {
            const int q = (c + 1) & 1;
            uint4 u;
            u.x = f2tf32(ra0.x); u.y = f2tf32(ra0.y); u.z = f2tf32(ra0.z); u.w = f2tf32(ra0.w);
            *(uint4*)&As[q][lr0 * LDS_STRIDE + lc] = u;
            u.x = f2tf32(ra1.x); u.y = f2tf32(ra1.y); u.z = f2tf32(ra1.z); u.w = f2tf32(ra1.w);
            *(uint4*)&As[q][lr1 * LDS_STRIDE + lc] = u;
            u.x = f2tf32(rb0.x); u.y = f2tf32(rb0.y); u.z = f2tf32(rb0.z); u.w = f2tf32(rb0.w);
            *(uint4*)&Bs[q][lr0 * LDS_STRIDE + lc] = u;
            u.x = f2tf32(rb1.x); u.y = f2tf32(rb1.y); u.z = f2tf32(rb1.z); u.w = f2tf32(rb1.w);
            *(uint4*)&Bs[q][lr1 * LDS_STRIDE + lc] = u;
        }
    }

    #pragma unroll
    for (int mt = 0; mt < 4; mt++) {
        #pragma unroll
        for (int nt = 0; nt < 4; nt++) {
            const int col = cT + wn * 32 + nt * 8 + 2 * t;
            const float bx = bias[col], by = bias[col + 1];
            #pragma unroll
            for (int half = 0; half < 2; half++) {
                const int row = rT + wm * 64 + mt * 16 + g + half * 8;
                float2 o;
                o.x = acc[mt][nt][half * 2 + 0] + bx;
                o.y = acc[mt][nt][half * 2 + 1] + by;
                if (mode == 0) {
                    const int h = col >> 6, dk = col & 63;
                    const int s = row >> 1, b = row & 1;
                    *(float2*)&out[(((size_t)(h * NB + b) * NS + s) << 6) + dk] = o;
                } else {
                    *(float2*)&out[(size_t)row * DM + col] = o;
                }
            }
        }
    }
}

// ---------------------------------------------------------------------------
// Flash attention with tf32 mma.sync.
// CTA: 128 q-rows of one (h,b); 256 threads (8 warps x 16 rows).
// Per 64-key tile: S = Q K^T (mma), online softmax, O += P V (mma).
// Strides chosen for conflict-free B-fragment LDS: K/P stride 68 (bank=4g+t),
// V natural layout stride 72 (bank=8t+g).
// ---------------------------------------------------------------------------
#define TQ 128
#define KS_STRIDE 68
#define VS_STRIDE 72
#define PS_STRIDE 68
#define KS_OFF 0
#define VS_OFF (64 * KS_STRIDE)                 // 4352
#define PS_OFF (VS_OFF + 64 * VS_STRIDE)        // 8960
#define ATT_SMEM_U32 (PS_OFF + TQ * PS_STRIDE)  // 17664
#define ATT_SMEM_BYTES (ATT_SMEM_U32 * 4)       // 70656

__global__ __launch_bounds__(256, 1)
void attn_mma_kernel(const float* __restrict__ Qg_,
                     const float* __restrict__ Kg_,
                     const float* __restrict__ Vg_,
                     float* __restrict__ ctx)
{
    extern __shared__ uint32_t sm[];

    const int tid = threadIdx.x;
    const int wid = tid >> 5, lid = tid & 31;
    const int g   = lid >> 2, t = lid & 3;
    const int wrow = wid * 16;
    const int qt = blockIdx.x;
    const int hb = blockIdx.y;

    const float* Qg = Qg_ + ((size_t)hb * NS << 6);
    const float* Kg = Kg_ + ((size_t)hb * NS << 6);
    const float* Vg = Vg_ + ((size_t)hb * NS << 6);

    // Stage Q (scaled by 1/8) into Ps area as floats, then build A frags in regs
    float* Qf = (float*)(sm + PS_OFF);
    #pragma unroll
    for (int it = 0; it < 8; it++) {
        const int flat = it * 256 + tid;      // < 2048
        const int row = flat >> 4, d0 = (flat & 15) * 4;
        float4 q4 = *(const float4*)&Qg[((size_t)(qt * TQ + row) << 6) + d0];
        q4.x *= 0.125f; q4.y *= 0.125f; q4.z *= 0.125f; q4.w *= 0.125f;
        *(float4*)&Qf[row * PS_STRIDE + d0] = q4;
    }
    __syncthreads();

    uint32_t qa[8][4];
    #pragma unroll
    for (int ks = 0; ks < 8; ks++) {
        qa[ks][0] = f2tf32(Qf[(wrow + g)     * PS_STRIDE + ks * 8 + t]);
        qa[ks][1] = f2tf32(Qf[(wrow + g + 8) * PS_STRIDE + ks * 8 + t]);
        qa[ks][2] = f2tf32(Qf[(wrow + g)     * PS_STRIDE + ks * 8 + t + 4]);
        qa[ks][3] = f2tf32(Qf[(wrow + g + 8) * PS_STRIDE + ks * 8 + t + 4]);
    }

    float oacc[8][4] = {};
    float m0 = -1e30f, m1 = -1e30f, l0 = 0.f, l1 = 0.f;

    for (int kt = 0; kt < NS / 64; kt++) {
        __syncthreads();   // prev PV reads (and Q-frag build on iter 0) complete
        // Load K (stride 68) and V (natural, stride 72) tiles as tf32
        #pragma unroll
        for (int it = 0; it < 4; it++) {
            const int flat = it * 256 + tid;  // < 1024
            const int key = flat >> 4, d0 = (flat & 15) * 4;
            float4 k4 = *(const float4*)&Kg[((size_t)(kt * 64 + key) << 6) + d0];
            uint4 ku;
            ku.x = f2tf32(k4.x); ku.y = f2tf32(k4.y); ku.z = f2tf32(k4.z); ku.w = f2tf32(k4.w);
            *(uint4*)&sm[KS_OFF + key * KS_STRIDE + d0] = ku;
            float4 v4 = *(const float4*)&Vg[((size_t)(kt * 64 + key) << 6) + d0];
            uint4 vu;
            vu.x = f2tf32(v4.x); vu.y = f2tf32(v4.y); vu.z = f2tf32(v4.z); vu.w = f2tf32(v4.w);
            *(uint4*)&sm[VS_OFF + key * VS_STRIDE + d0] = vu;
        }
        __syncthreads();

        // S = Q K^T (scaled)
        float sacc[8][4] = {};
        #pragma unroll
        for (int nt = 0; nt < 8; nt++) {
            const uint32_t* krow = &sm[KS_OFF + (nt * 8 + g) * KS_STRIDE + t];
            #pragma unroll
            for (int ks = 0; ks < 8; ks++) {
                uint32_t b[2];
                b[0] = krow[ks * 8];
                b[1] = krow[ks * 8 + 4];
                mma_tf32(sacc[nt], qa[ks], b);
            }
        }

        // Online softmax (rows g and g+8 of this warp's 16-row slab)
        float mx0 = -1e30f, mx1 = -1e30f;
        #pragma unroll
        for (int nt = 0; nt < 8; nt++) {
            mx0 = fmaxf(mx0, fmaxf(sacc[nt][0], sacc[nt][1]));
            mx1 = fmaxf(mx1, fmaxf(sacc[nt][2], sacc[nt][3]));
        }
        mx0 = fmaxf(mx0, __shfl_xor_sync(0xffffffffu, mx0, 1));
        mx0 = fmaxf(mx0, __shfl_xor_sync(0xffffffffu, mx0, 2));
        mx1 = fmaxf(mx1, __shfl_xor_sync(0xffffffffu, mx1, 1));
        mx1 = fmaxf(mx1, __shfl_xor_sync(0xffffffffu, mx1, 2));
        const float mn0 = fmaxf(m0, mx0), mn1 = fmaxf(m1, mx1);
        const float c0 = __expf(m0 - mn0), c1 = __expf(m1 - mn1);
        m0 = mn0; m1 = mn1;

        float s0 = 0.f, s1 = 0.f;
        #pragma unroll
        for (int nt = 0; nt < 8; nt++) {
            const float e0 = __expf(sacc[nt][0] - mn0);
            const float e1 = __expf(sacc[nt][1] - mn0);
            const float e2 = __expf(sacc[nt][2] - mn1);
            const float e3 = __expf(sacc[nt][3] - mn1);
            s0 += e0 + e1; s1 += e2 + e3;
            uint2 p;
            p.x = f2tf32(e0); p.y = f2tf32(e1);
            *(uint2*)&sm[PS_OFF + (wrow + g) * PS_STRIDE + nt * 8 + 2 * t] = p;
            p.x = f2tf32(e2); p.y = f2tf32(e3);
            *(uint2*)&sm[PS_OFF + (wrow + g + 8) * PS_STRIDE + nt * 8 + 2 * t] = p;
            oacc[nt][0] *= c0; oacc[nt][1] *= c0;
            oacc[nt][2] *= c1; oacc[nt][3] *= c1;
        }
        s0 += __shfl_xor_sync(0xffffffffu, s0, 1);
        s0 += __shfl_xor_sync(0xffffffffu, s0, 2);
        s1 += __shfl_xor_sync(0xffffffffu, s1, 1);
        s1 += __shfl_xor_sync(0xffffffffu, s1, 2);
        l0 = l0 * c0 + s0;
        l1 = l1 * c1 + s1;
        __syncwarp();   // this warp's P rows written before its own A-frag reads

        // O += P V
        #pragma unroll
        for (int ks = 0; ks < 8; ks++) {
            uint32_t pa[4];
            pa[0] = sm[PS_OFF + (wrow + g)     * PS_STRIDE + ks * 8 + t];
            pa[1] = sm[PS_OFF + (wrow + g + 8) * PS_STRIDE + ks * 8 + t];
            pa[2] = sm[PS_OFF + (wrow + g)     * PS_STRIDE + ks * 8 + t + 4];
            pa[3] = sm[PS_OFF + (wrow + g + 8) * PS_STRIDE + ks * 8 + t + 4];
            const uint32_t* vrow0 = &sm[VS_OFF + (ks * 8 + t)     * VS_STRIDE + g];
            const uint32_t* vrow1 = &sm[VS_OFF + (ks * 8 + t + 4) * VS_STRIDE + g];
            #pragma unroll
            for (int nt = 0; nt < 8; nt++) {
                uint32_t b[2];
                b[0] = vrow0[nt * 8];
                b[1] = vrow1[nt * 8];
                mma_tf32(oacc[nt], pa, b);
            }
        }
    }

    // Epilogue: O /= l -> ctx[s*NB+b][h*64+dk]
    const float inv0 = 1.f / l0, inv1 = 1.f / l1;
    const int h = hb >> 1, b = hb & 1;
    const int s_0 = qt * TQ + wrow + g;
    const int s_1 = s_0 + 8;
    #pragma unroll
    for (int nt = 0; nt < 8; nt++) {
        const int col = (h << 6) + nt * 8 + 2 * t;
        float2 o;
        o.x = oacc[nt][0] * inv0; o.y = oacc[nt][1] * inv0;
        *(float2*)&ctx[(size_t)(s_0 * NB + b) * DM + col] = o;
        o.x = oacc[nt][2] * inv1; o.y = oacc[nt][3] * inv1;
        *(float2*)&ctx[(size_t)(s_1 * NB + b) * DM + col] = o;
    }
}

// ---------------------------------------------------------------------------
extern "C" void kernel_launch(void* const* d_in, const int* in_sizes, int n_in,
                              void* d_out, int out_size)
{
    const float* query = (const float*)d_in[0];
    const float* key_  = (const float*)d_in[1];
    const float* value = (const float*)d_in[2];
    const float* Wq = (const float*)d_in[3];
    const float* bq = (const float*)d_in[4];
    const float* Wk = (const float*)d_in[5];
    const float* bk = (const float*)d_in[6];
    const float* Wv = (const float*)d_in[7];
    const float* bv = (const float*)d_in[8];
    const float* Wo = (const float*)d_in[9];
    const float* bo = (const float*)d_in[10];
    float* out = (float*)d_out;

    float *pQ, *pK, *pV, *pC;
    cudaGetSymbolAddress((void**)&pQ, g_Q);
    cudaGetSymbolAddress((void**)&pK, g_K);
    cudaGetSymbolAddress((void**)&pV, g_V);
    cudaGetSymbolAddress((void**)&pC, g_ctx);

    cudaFuncSetAttribute(attn_mma_kernel,
                         cudaFuncAttributeMaxDynamicSharedMemorySize, ATT_SMEM_BYTES);

    dim3 gg(DM / BN, NROWS / BM);   // 8 x 32 = 256 CTAs
    gemm_mma_kernel<<<gg, 256>>>(query, Wq, bq, pQ, 0);
    gemm_mma_kernel<<<gg, 256>>>(key_,  Wk, bk, pK, 0);
    gemm_mma_kernel<<<gg, 256>>>(value, Wv, bv, pV, 0);

    attn_mma_kernel<<<dim3(NS / TQ, NH * NB), 256, ATT_SMEM_BYTES>>>(pQ, pK, pV, pC);

    gemm_mma_kernel<<<gg, 256>>>(pC, Wo, bo, out, 1);
}

// round 5
// speedup vs baseline: 3.4046x; 1.1025x over previous
#include <cuda_runtime.h>
#include <cstdint>
#include <math.h>

#define NH 16
#define NB 2
#define NS 2048
#define DM 1024
#define DK 64
#define NROWS (NS*NB)   // 4096

// Scratch (allocation-free rule: __device__ globals)
__device__ __align__(16) float g_Q[NH*NB*NS*DK];
__device__ __align__(16) float g_K[NH*NB*NS*DK];
__device__ __align__(16) float g_V[NH*NB*NS*DK];
__device__ __align__(16) float g_ctx[(size_t)NROWS*DM];

// ---------------------------------------------------------------------------
// tf32 helpers (portable mma.sync path — compute_103 has no tcgen05)
// ---------------------------------------------------------------------------
__device__ __forceinline__ uint32_t f2tf32(float f) {
    uint32_t o;
    asm("cvt.rna.tf32.f32 %0, %1;" : "=r"(o) : "f"(f));
    return o;
}

__device__ __forceinline__ void mma_tf32(float c[4], const uint32_t a[4], const uint32_t b[2]) {
    asm volatile(
        "mma.sync.aligned.m16n8k8.row.col.f32.tf32.tf32.f32 "
        "{%0,%1,%2,%3}, {%4,%5,%6,%7}, {%8,%9}, {%0,%1,%2,%3};"
        : "+f"(c[0]), "+f"(c[1]), "+f"(c[2]), "+f"(c[3])
        : "r"(a[0]), "r"(a[1]), "r"(a[2]), "r"(a[3]), "r"(b[0]), "r"(b[1]));
}

__device__ __forceinline__ uint4 cvt4(float4 v) {
    uint4 u;
    u.x = f2tf32(v.x); u.y = f2tf32(v.y); u.z = f2tf32(v.z); u.w = f2tf32(v.w);
    return u;
}

// ---------------------------------------------------------------------------
// tf32 mma.sync NT GEMM body: out = X[.,DM] @ W[DM,DM]^T + bias
// CTA tile 128x128, K-chunk 16, 256 threads = 8 warps (2x4), warp tile 64x32.
// MODE 0: scatter into [h, b, s, dk] layout; MODE 1: row-major [NROWS, DM]
// ---------------------------------------------------------------------------
#define BM 128
#define BN 128
#define BK 16
#define LDS_STRIDE 20

template<int MODE>
__device__ __forceinline__ void gemm_body(const float* __restrict__ X,
                                          const float* __restrict__ W,
                                          const float* __restrict__ bias,
                                          float* __restrict__ out,
                                          int rT, int cT)
{
    __shared__ __align__(16) uint32_t As[2][BM * LDS_STRIDE];
    __shared__ __align__(16) uint32_t Bs[2][BN * LDS_STRIDE];

    const int tid = threadIdx.x;
    const int wid = tid >> 5, lid = tid & 31;
    const int wm  = wid >> 2;
    const int wn  = wid & 3;
    const int g   = lid >> 2;
    const int t   = lid & 3;

    const int lr0 = (tid * 4) >> 4;
    const int lr1 = lr0 + 64;
    const int lc  = (tid * 4) & 15;

    float acc[4][4][4] = {};
    float4 ra0, ra1, rb0, rb1;

    ra0 = *(const float4*)&X[(size_t)(rT + lr0) * DM + lc];
    ra1 = *(const float4*)&X[(size_t)(rT + lr1) * DM + lc];
    rb0 = *(const float4*)&W[(size_t)(cT + lr0) * DM + lc];
    rb1 = *(const float4*)&W[(size_t)(cT + lr1) * DM + lc];
    *(uint4*)&As[0][lr0 * LDS_STRIDE + lc] = cvt4(ra0);
    *(uint4*)&As[0][lr1 * LDS_STRIDE + lc] = cvt4(ra1);
    *(uint4*)&Bs[0][lr0 * LDS_STRIDE + lc] = cvt4(rb0);
    *(uint4*)&Bs[0][lr1 * LDS_STRIDE + lc] = cvt4(rb1);

    const int NCHUNK = DM / BK;
    for (int c = 0; c < NCHUNK; c++) {
        const int p = c & 1;
        __syncthreads();

        if (c + 1 < NCHUNK) {
            const int kk = (c + 1) << 4;
            ra0 = *(const float4*)&X[(size_t)(rT + lr0) * DM + kk + lc];
            ra1 = *(const float4*)&X[(size_t)(rT + lr1) * DM + kk + lc];
            rb0 = *(const float4*)&W[(size_t)(cT + lr0) * DM + kk + lc];
            rb1 = *(const float4*)&W[(size_t)(cT + lr1) * DM + kk + lc];
        }

        #pragma unroll
        for (int ks = 0; ks < BK; ks += 8) {
            uint32_t a[4][4], b[4][2];
            #pragma unroll
            for (int mt = 0; mt < 4; mt++) {
                const int row = wm * 64 + mt * 16 + g;
                a[mt][0] = As[p][row * LDS_STRIDE + ks + t];
                a[mt][1] = As[p][(row + 8) * LDS_STRIDE + ks + t];
                a[mt][2] = As[p][row * LDS_STRIDE + ks + t + 4];
                a[mt][3] = As[p][(row + 8) * LDS_STRIDE + ks + t + 4];
            }
            #pragma unroll
            for (int nt = 0; nt < 4; nt++) {
                const int col = wn * 32 + nt * 8 + g;
                b[nt][0] = Bs[p][col * LDS_STRIDE + ks + t];
                b[nt][1] = Bs[p][col * LDS_STRIDE + ks + t + 4];
            }
            #pragma unroll
            for (int mt = 0; mt < 4; mt++)
                #pragma unroll
                for (int nt = 0; nt < 4; nt++)
                    mma_tf32(acc[mt][nt], a[mt], b[nt]);
        }

        if (c + 1 < NCHUNK) {
            const int q = (c + 1) & 1;
            *(uint4*)&As[q][lr0 * LDS_STRIDE + lc] = cvt4(ra0);
            *(uint4*)&As[q][lr1 * LDS_STRIDE + lc] = cvt4(ra1);
            *(uint4*)&Bs[q][lr0 * LDS_STRIDE + lc] = cvt4(rb0);
            *(uint4*)&Bs[q][lr1 * LDS_STRIDE + lc] = cvt4(rb1);
        }
    }

    #pragma unroll
    for (int mt = 0; mt < 4; mt++) {
        #pragma unroll
        for (int nt = 0; nt < 4; nt++) {
            const int col = cT + wn * 32 + nt * 8 + 2 * t;
            const float bx = bias[col], by = bias[col + 1];
            #pragma unroll
            for (int half = 0; half < 2; half++) {
                const int row = rT + wm * 64 + mt * 16 + g + half * 8;
                float2 o;
                o.x = acc[mt][nt][half * 2 + 0] + bx;
                o.y = acc[mt][nt][half * 2 + 1] + by;
                if (MODE == 0) {
                    const int h = col >> 6, dk = col & 63;
                    const int s = row >> 1, b = row & 1;
                    *(float2*)&out[(((size_t)(h * NB + b) * NS + s) << 6) + dk] = o;
                } else {
                    *(float2*)&out[(size_t)row * DM + col] = o;
                }
            }
        }
    }
}

// Fused Q/K/V projection: blockIdx.z selects (input, weight, bias, output)
__global__ __launch_bounds__(256, 2)
void qkv_gemm_kernel(const float* __restrict__ q, const float* __restrict__ k,
                     const float* __restrict__ v,
                     const float* __restrict__ Wq, const float* __restrict__ Wk,
                     const float* __restrict__ Wv,
                     const float* __restrict__ bq, const float* __restrict__ bk,
                     const float* __restrict__ bv,
                     float* oq, float* ok, float* ov)
{
    const float *X, *W, *B;
    float* O;
    if (blockIdx.z == 0)      { X = q; W = Wq; B = bq; O = oq; }
    else if (blockIdx.z == 1) { X = k; W = Wk; B = bk; O = ok; }
    else                      { X = v; W = Wv; B = bv; O = ov; }
    gemm_body<0>(X, W, B, O, blockIdx.y << 7, blockIdx.x << 7);
}

__global__ __launch_bounds__(256, 2)
void out_gemm_kernel(const float* __restrict__ X, const float* __restrict__ W,
                     const float* __restrict__ B, float* O)
{
    gemm_body<1>(X, W, B, O, blockIdx.y << 7, blockIdx.x << 7);
}

// ---------------------------------------------------------------------------
// Flash attention with tf32 mma.sync + register-prefetch pipeline.
// CTA: 128 q-rows of one (h,b); 256 threads (8 warps x 16 rows).
// Tile kt: STS regs->smem (cvt once, reused by 8 warps), LDG tile kt+1 into
// regs, then S=QK^T (mma), online softmax, O+=PV (mma). LDG latency hidden
// under the tile's compute. Strides: K/P 68 (bank=4g+t), V 72 (bank=8t+g),
// all conflict-free for B-fragment LDS.
// ---------------------------------------------------------------------------
#define TQ 128
#define KS_STRIDE 68
#define VS_STRIDE 72
#define PS_STRIDE 68
#define KS_OFF 0
#define VS_OFF (64 * KS_STRIDE)                 // 4352
#define PS_OFF (VS_OFF + 64 * VS_STRIDE)        // 8960
#define ATT_SMEM_U32 (PS_OFF + TQ * PS_STRIDE)  // 17664
#define ATT_SMEM_BYTES (ATT_SMEM_U32 * 4)       // 70656

__global__ __launch_bounds__(256, 1)
void attn_mma_kernel(const float* __restrict__ Qg_,
                     const float* __restrict__ Kg_,
                     const float* __restrict__ Vg_,
                     float* __restrict__ ctx)
{
    extern __shared__ uint32_t sm[];

    const int tid = threadIdx.x;
    const int wid = tid >> 5, lid = tid & 31;
    const int g   = lid >> 2, t = lid & 3;
    const int wrow = wid * 16;
    const int qt = blockIdx.x;
    const int hb = blockIdx.y;

    const float* Qg = Qg_ + ((size_t)hb * NS << 6);
    const float* Kg = Kg_ + ((size_t)hb * NS << 6);
    const float* Vg = Vg_ + ((size_t)hb * NS << 6);

    // Stage Q (scaled by 1/8) into Ps area as floats, then build A frags in regs
    float* Qf = (float*)(sm + PS_OFF);
    #pragma unroll
    for (int it = 0; it < 8; it++) {
        const int flat = it * 256 + tid;      // < 2048
        const int row = flat >> 4, d0 = (flat & 15) * 4;
        float4 q4 = *(const float4*)&Qg[((size_t)(qt * TQ + row) << 6) + d0];
        q4.x *= 0.125f; q4.y *= 0.125f; q4.z *= 0.125f; q4.w *= 0.125f;
        *(float4*)&Qf[row * PS_STRIDE + d0] = q4;
    }
    __syncthreads();

    uint32_t qa[8][4];
    #pragma unroll
    for (int ks = 0; ks < 8; ks++) {
        qa[ks][0] = f2tf32(Qf[(wrow + g)     * PS_STRIDE + ks * 8 + t]);
        qa[ks][1] = f2tf32(Qf[(wrow + g + 8) * PS_STRIDE + ks * 8 + t]);
        qa[ks][2] = f2tf32(Qf[(wrow + g)     * PS_STRIDE + ks * 8 + t + 4]);
        qa[ks][3] = f2tf32(Qf[(wrow + g + 8) * PS_STRIDE + ks * 8 + t + 4]);
    }

    // Per-thread K/V load coords (fixed across tiles)
    int lkey[4], ld0[4];
    #pragma unroll
    for (int it = 0; it < 4; it++) {
        const int flat = it * 256 + tid;      // < 1024
        lkey[it] = flat >> 4;
        ld0[it]  = (flat & 15) * 4;
    }

    // Preload tile 0 into registers
    float4 kreg[4], vreg[4];
    #pragma unroll
    for (int it = 0; it < 4; it++) {
        kreg[it] = *(const float4*)&Kg[((size_t)lkey[it] << 6) + ld0[it]];
        vreg[it] = *(const float4*)&Vg[((size_t)lkey[it] << 6) + ld0[it]];
    }

    float oacc[8][4] = {};
    float m0 = -1e30f, m1 = -1e30f, l0 = 0.f, l1 = 0.f;

    const int NT = NS / 64;
    for (int kt = 0; kt < NT; kt++) {
        __syncthreads();   // all warps done reading K/V smem of prev tile
        #pragma unroll
        for (int it = 0; it < 4; it++) {
            *(uint4*)&sm[KS_OFF + lkey[it] * KS_STRIDE + ld0[it]] = cvt4(kreg[it]);
            *(uint4*)&sm[VS_OFF + lkey[it] * VS_STRIDE + ld0[it]] = cvt4(vreg[it]);
        }
        __syncthreads();

        // Prefetch next tile into registers (latency hidden by compute below)
        if (kt + 1 < NT) {
            #pragma unroll
            for (int it = 0; it < 4; it++) {
                const size_t base = ((size_t)((kt + 1) * 64 + lkey[it]) << 6) + ld0[it];
                kreg[it] = *(const float4*)&Kg[base];
                vreg[it] = *(const float4*)&Vg[base];
            }
        }

        // S = Q K^T (scaled)
        float sacc[8][4] = {};
        #pragma unroll
        for (int nt = 0; nt < 8; nt++) {
            const uint32_t* krow = &sm[KS_OFF + (nt * 8 + g) * KS_STRIDE + t];
            #pragma unroll
            for (int ks = 0; ks < 8; ks++) {
                uint32_t b[2];
                b[0] = krow[ks * 8];
                b[1] = krow[ks * 8 + 4];
                mma_tf32(sacc[nt], qa[ks], b);
            }
        }

        // Online softmax (rows g and g+8 of this warp's 16-row slab)
        float mx0 = -1e30f, mx1 = -1e30f;
        #pragma unroll
        for (int nt = 0; nt < 8; nt++) {
            mx0 = fmaxf(mx0, fmaxf(sacc[nt][0], sacc[nt][1]));
            mx1 = fmaxf(mx1, fmaxf(sacc[nt][2], sacc[nt][3]));
        }
        mx0 = fmaxf(mx0, __shfl_xor_sync(0xffffffffu, mx0, 1));
        mx0 = fmaxf(mx0, __shfl_xor_sync(0xffffffffu, mx0, 2));
        mx1 = fmaxf(mx1, __shfl_xor_sync(0xffffffffu, mx1, 1));
        mx1 = fmaxf(mx1, __shfl_xor_sync(0xffffffffu, mx1, 2));
        const float mn0 = fmaxf(m0, mx0), mn1 = fmaxf(m1, mx1);
        const float c0 = __expf(m0 - mn0), c1 = __expf(m1 - mn1);
        m0 = mn0; m1 = mn1;

        float s0 = 0.f, s1 = 0.f;
        #pragma unroll
        for (int nt = 0; nt < 8; nt++) {
            const float e0 = __expf(sacc[nt][0] - mn0);
            const float e1 = __expf(sacc[nt][1] - mn0);
            const float e2 = __expf(sacc[nt][2] - mn1);
            const float e3 = __expf(sacc[nt][3] - mn1);
            s0 += e0 + e1; s1 += e2 + e3;
            uint2 p;
            p.x = f2tf32(e0); p.y = f2tf32(e1);
            *(uint2*)&sm[PS_OFF + (wrow + g) * PS_STRIDE + nt * 8 + 2 * t] = p;
            p.x = f2tf32(e2); p.y = f2tf32(e3);
            *(uint2*)&sm[PS_OFF + (wrow + g + 8) * PS_STRIDE + nt * 8 + 2 * t] = p;
            oacc[nt][0] *= c0; oacc[nt][1] *= c0;
            oacc[nt][2] *= c1; oacc[nt][3] *= c1;
        }
        s0 += __shfl_xor_sync(0xffffffffu, s0, 1);
        s0 += __shfl_xor_sync(0xffffffffu, s0, 2);
        s1 += __shfl_xor_sync(0xffffffffu, s1, 1);
        s1 += __shfl_xor_sync(0xffffffffu, s1, 2);
        l0 = l0 * c0 + s0;
        l1 = l1 * c1 + s1;
        __syncwarp();   // this warp's P rows written before its own A-frag reads

        // O += P V
        #pragma unroll
        for (int ks = 0; ks < 8; ks++) {
            uint32_t pa[4];
            pa[0] = sm[PS_OFF + (wrow + g)     * PS_STRIDE + ks * 8 + t];
            pa[1] = sm[PS_OFF + (wrow + g + 8) * PS_STRIDE + ks * 8 + t];
            pa[2] = sm[PS_OFF + (wrow + g)     * PS_STRIDE + ks * 8 + t + 4];
            pa[3] = sm[PS_OFF + (wrow + g + 8) * PS_STRIDE + ks * 8 + t + 4];
            const uint32_t* vrow0 = &sm[VS_OFF + (ks * 8 + t)     * VS_STRIDE + g];
            const uint32_t* vrow1 = &sm[VS_OFF + (ks * 8 + t + 4) * VS_STRIDE + g];
            #pragma unroll
            for (int nt = 0; nt < 8; nt++) {
                uint32_t b[2];
                b[0] = vrow0[nt * 8];
                b[1] = vrow1[nt * 8];
                mma_tf32(oacc[nt], pa, b);
            }
        }
    }

    // Epilogue: O /= l -> ctx[s*NB+b][h*64+dk]
    const float inv0 = 1.f / l0, inv1 = 1.f / l1;
    const int h = hb >> 1, b = hb & 1;
    const int s_0 = qt * TQ + wrow + g;
    const int s_1 = s_0 + 8;
    #pragma unroll
    for (int nt = 0; nt < 8; nt++) {
        const int col = (h << 6) + nt * 8 + 2 * t;
        float2 o;
        o.x = oacc[nt][0] * inv0; o.y = oacc[nt][1] * inv0;
        *(float2*)&ctx[(size_t)(s_0 * NB + b) * DM + col] = o;
        o.x = oacc[nt][2] * inv1; o.y = oacc[nt][3] * inv1;
        *(float2*)&ctx[(size_t)(s_1 * NB + b) * DM + col] = o;
    }
}

// ---------------------------------------------------------------------------
extern "C" void kernel_launch(void* const* d_in, const int* in_sizes, int n_in,
                              void* d_out, int out_size)
{
    const float* query = (const float*)d_in[0];
    const float* key_  = (const float*)d_in[1];
    const float* value = (const float*)d_in[2];
    const float* Wq = (const float*)d_in[3];
    const float* bq = (const float*)d_in[4];
    const float* Wk = (const float*)d_in[5];
    const float* bk = (const float*)d_in[6];
    const float* Wv = (const float*)d_in[7];
    const float* bv = (const float*)d_in[8];
    const float* Wo = (const float*)d_in[9];
    const float* bo = (const float*)d_in[10];
    float* out = (float*)d_out;

    float *pQ, *pK, *pV, *pC;
    cudaGetSymbolAddress((void**)&pQ, g_Q);
    cudaGetSymbolAddress((void**)&pK, g_K);
    cudaGetSymbolAddress((void**)&pV, g_V);
    cudaGetSymbolAddress((void**)&pC, g_ctx);

    cudaFuncSetAttribute(attn_mma_kernel,
                         cudaFuncAttributeMaxDynamicSharedMemorySize, ATT_SMEM_BYTES);

    dim3 gq(DM / BN, NROWS / BM, 3);   // 8 x 32 x 3 = 768 CTAs
    qkv_gemm_kernel<<<gq, 256>>>(query, key_, value, Wq, Wk, Wv, bq, bk, bv, pQ, pK, pV);

    attn_mma_kernel<<<dim3(NS / TQ, NH * NB), 256, ATT_SMEM_BYTES>>>(pQ, pK, pV, pC);

    dim3 gg(DM / BN, NROWS / BM);      // 8 x 32 = 256 CTAs
    out_gemm_kernel<<<gg, 256>>>(pC, Wo, bo, out);
}

// round 7
// speedup vs baseline: 3.7121x; 1.0903x over previous
#include <cuda_runtime.h>
#include <cstdint>
#include <math.h>

#define NH 16
#define NB 2
#define NS 2048
#define DM 1024
#define DK 64
#define NROWS (NS*NB)   // 4096

// Scratch (allocation-free rule: __device__ globals)
__device__ __align__(16) float g_Q[NH*NB*NS*DK];
__device__ __align__(16) float g_K[NH*NB*NS*DK];
__device__ __align__(16) float g_V[NH*NB*NS*DK];
__device__ __align__(16) float g_ctx[(size_t)NROWS*DM];

// ---------------------------------------------------------------------------
// helpers (portable mma.sync path — compute_103 has no tcgen05)
// ---------------------------------------------------------------------------
__device__ __forceinline__ uint32_t f2tf32(float f) {
    uint32_t o;
    asm("cvt.rna.tf32.f32 %0, %1;" : "=r"(o) : "f"(f));
    return o;
}
__device__ __forceinline__ float ex2(float x) {
    float r;
    asm("ex2.approx.ftz.f32 %0, %1;" : "=f"(r) : "f"(x));
    return r;
}
__device__ __forceinline__ void mma_tf32(float c[4], const uint32_t a[4], const uint32_t b[2]) {
    asm volatile(
        "mma.sync.aligned.m16n8k8.row.col.f32.tf32.tf32.f32 "
        "{%0,%1,%2,%3}, {%4,%5,%6,%7}, {%8,%9}, {%0,%1,%2,%3};"
        : "+f"(c[0]), "+f"(c[1]), "+f"(c[2]), "+f"(c[3])
        : "r"(a[0]), "r"(a[1]), "r"(a[2]), "r"(a[3]), "r"(b[0]), "r"(b[1]));
}
__device__ __forceinline__ uint4 cvt4(float4 v) {
    uint4 u;
    u.x = f2tf32(v.x); u.y = f2tf32(v.y); u.z = f2tf32(v.z); u.w = f2tf32(v.w);
    return u;
}
__device__ __forceinline__ uint32_t smem_u32(const void* p) {
    uint32_t a;
    asm("{ .reg .u64 t; cvta.to.shared.u64 t, %1; cvt.u32.u64 %0, t; }" : "=r"(a) : "l"(p));
    return a;
}
__device__ __forceinline__ void cp_async16(uint32_t dst, const void* src) {
    asm volatile("cp.async.cg.shared.global [%0], [%1], 16;" :: "r"(dst), "l"(src));
}
__device__ __forceinline__ void cp_commit() { asm volatile("cp.async.commit_group;" ::: "memory"); }
template<int N> __device__ __forceinline__ void cp_wait() {
    asm volatile("cp.async.wait_group %0;" :: "n"(N) : "memory");
}

// ---------------------------------------------------------------------------
// tf32 mma.sync NT GEMM: out = X[.,DM] @ W[DM,DM]^T + bias
// 128x128 tile, BK=16, 256 thr / 8 warps (2x4), warp 64x32.
// 4-stage cp.async pipeline, raw fp32 in smem, cvt.rna at fragment build.
// MODE 0: scatter into [h, b, s, dk]; MODE 1: row-major [NROWS, DM]
// ---------------------------------------------------------------------------
#define BM 128
#define BN 128
#define BK 16
#define LDS_STRIDE 20
#define STG_U32 (BM * LDS_STRIDE)          // 2560 per stage per matrix
#define STAGES 4
#define GSMEM_BYTES (STAGES * STG_U32 * 4 * 2)   // 81920

template<int MODE>
__device__ __forceinline__ void gemm_body(const float* __restrict__ X,
                                          const float* __restrict__ W,
                                          const float* __restrict__ bias,
                                          float* __restrict__ out,
                                          int rT, int cT)
{
    extern __shared__ uint32_t dyn[];
    float* As = (float*)dyn;
    float* Bs = (float*)(dyn + STAGES * STG_U32);

    const int tid = threadIdx.x;
    const int wid = tid >> 5, lid = tid & 31;
    const int wm  = wid >> 2;
    const int wn  = wid & 3;
    const int g   = lid >> 2;
    const int t   = lid & 3;

    const int lr0 = (tid * 4) >> 4;
    const int lr1 = lr0 + 64;
    const int lc  = (tid * 4) & 15;

    const uint32_t aB = smem_u32(As), bB = smem_u32(Bs);
    const uint32_t off0 = (uint32_t)(lr0 * LDS_STRIDE + lc) * 4;
    const uint32_t off1 = (uint32_t)(lr1 * LDS_STRIDE + lc) * 4;
    const uint32_t SSB  = STG_U32 * 4;
    const float* xr0 = &X[(size_t)(rT + lr0) * DM + lc];
    const float* xr1 = &X[(size_t)(rT + lr1) * DM + lc];
    const float* wr0 = &W[(size_t)(cT + lr0) * DM + lc];
    const float* wr1 = &W[(size_t)(cT + lr1) * DM + lc];

    #pragma unroll
    for (int s = 0; s < STAGES - 1; s++) {
        const int kk = s << 4;
        cp_async16(aB + s * SSB + off0, xr0 + kk);
        cp_async16(aB + s * SSB + off1, xr1 + kk);
        cp_async16(bB + s * SSB + off0, wr0 + kk);
        cp_async16(bB + s * SSB + off1, wr1 + kk);
        cp_commit();
    }

    float acc[4][4][4] = {};
    const int NCHUNK = DM / BK;   // 64
    for (int c = 0; c < NCHUNK; c++) {
        cp_wait<STAGES - 2>();
        __syncthreads();

        if (c + STAGES - 1 < NCHUNK) {
            const int s = (c + STAGES - 1) & (STAGES - 1);
            const int kk = (c + STAGES - 1) << 4;
            cp_async16(aB + s * SSB + off0, xr0 + kk);
            cp_async16(aB + s * SSB + off1, xr1 + kk);
            cp_async16(bB + s * SSB + off0, wr0 + kk);
            cp_async16(bB + s * SSB + off1, wr1 + kk);
        }
        cp_commit();

        const float* Ap = As + (c & (STAGES - 1)) * STG_U32;
        const float* Bp = Bs + (c & (STAGES - 1)) * STG_U32;

        #pragma unroll
        for (int ks = 0; ks < BK; ks += 8) {
            uint32_t a[4][4], b[4][2];
            #pragma unroll
            for (int mt = 0; mt < 4; mt++) {
                const int row = wm * 64 + mt * 16 + g;
                a[mt][0] = f2tf32(Ap[row * LDS_STRIDE + ks + t]);
                a[mt][1] = f2tf32(Ap[(row + 8) * LDS_STRIDE + ks + t]);
                a[mt][2] = f2tf32(Ap[row * LDS_STRIDE + ks + t + 4]);
                a[mt][3] = f2tf32(Ap[(row + 8) * LDS_STRIDE + ks + t + 4]);
            }
            #pragma unroll
            for (int nt = 0; nt < 4; nt++) {
                const int col = wn * 32 + nt * 8 + g;
                b[nt][0] = f2tf32(Bp[col * LDS_STRIDE + ks + t]);
                b[nt][1] = f2tf32(Bp[col * LDS_STRIDE + ks + t + 4]);
            }
            #pragma unroll
            for (int mt = 0; mt < 4; mt++)
                #pragma unroll
                for (int nt = 0; nt < 4; nt++)
                    mma_tf32(acc[mt][nt], a[mt], b[nt]);
        }
    }

    #pragma unroll
    for (int mt = 0; mt < 4; mt++) {
        #pragma unroll
        for (int nt = 0; nt < 4; nt++) {
            const int col = cT + wn * 32 + nt * 8 + 2 * t;
            const float bx = bias[col], by = bias[col + 1];
            #pragma unroll
            for (int half = 0; half < 2; half++) {
                const int row = rT + wm * 64 + mt * 16 + g + half * 8;
                float2 o;
                o.x = acc[mt][nt][half * 2 + 0] + bx;
                o.y = acc[mt][nt][half * 2 + 1] + by;
                if (MODE == 0) {
                    const int h = col >> 6, dk = col & 63;
                    const int s = row >> 1, b = row & 1;
                    *(float2*)&out[(((size_t)(h * NB + b) * NS + s) << 6) + dk] = o;
                } else {
                    *(float2*)&out[(size_t)row * DM + col] = o;
                }
            }
        }
    }
}

__global__ __launch_bounds__(256, 2)
void qkv_gemm_kernel(const float* __restrict__ q, const float* __restrict__ k,
                     const float* __restrict__ v,
                     const float* __restrict__ Wq, const float* __restrict__ Wk,
                     const float* __restrict__ Wv,
                     const float* __restrict__ bq, const float* __restrict__ bk,
                     const float* __restrict__ bv,
                     float* oq, float* ok, float* ov)
{
    const float *X, *W, *B;
    float* O;
    if (blockIdx.z == 0)      { X = q; W = Wq; B = bq; O = oq; }
    else if (blockIdx.z == 1) { X = k; W = Wk; B = bk; O = ok; }
    else                      { X = v; W = Wv; B = bv; O = ov; }
    gemm_body<0>(X, W, B, O, blockIdx.y << 7, blockIdx.x << 7);
}

__global__ __launch_bounds__(256, 2)
void out_gemm_kernel(const float* __restrict__ X, const float* __restrict__ W,
                     const float* __restrict__ B, float* O)
{
    gemm_body<1>(X, W, B, O, blockIdx.y << 7, blockIdx.x << 7);
}

// ---------------------------------------------------------------------------
// Flash attention, tf32 mma.sync, occupancy-optimized:
// CTA = 64 q-rows of one (h,b), 128 threads / 4 warps (16 rows each).
// smem 53 KB -> 4 CTAs/SM; cross-CTA overlap hides load/softmax latency.
// Softmax in log2 domain (Q pre-scaled by 0.125*log2e, ex2.approx).
// Strides: K/P 68 (bank=4g+t), V 72 (bank=8t+g) — conflict-free.
// ---------------------------------------------------------------------------
#define TQ 64
#define KS_STRIDE 68
#define VS_STRIDE 72
#define PS_STRIDE 68
#define KS_OFF 0
#define VS_OFF (64 * KS_STRIDE)                 // 4352
#define PS_OFF (VS_OFF + 64 * VS_STRIDE)        // 8960
#define ATT_SMEM_U32 (PS_OFF + TQ * PS_STRIDE)  // 13312
#define ATT_SMEM_BYTES (ATT_SMEM_U32 * 4)       // 53248

#define QSCALE (0.125f * 1.4426950408889634f)

__global__ __launch_bounds__(128, 4)
void attn_mma_kernel(const float* __restrict__ Qg_,
                     const float* __restrict__ Kg_,
                     const float* __restrict__ Vg_,
                     float* __restrict__ ctx)
{
    extern __shared__ uint32_t sm[];

    const int tid = threadIdx.x;
    const int wid = tid >> 5, lid = tid & 31;
    const int g   = lid >> 2, t = lid & 3;
    const int wrow = wid * 16;
    const int qt = blockIdx.x;
    const int hb = blockIdx.y;

    const float* Qg = Qg_ + ((size_t)hb * NS << 6);
    const float* Kg = Kg_ + ((size_t)hb * NS << 6);
    const float* Vg = Vg_ + ((size_t)hb * NS << 6);

    // Stage Q (pre-scaled into log2 domain) into Ps area, build A frags
    float* Qf = (float*)(sm + PS_OFF);
    #pragma unroll
    for (int it = 0; it < 8; it++) {
        const int flat = it * 128 + tid;      // < 1024
        const int row = flat >> 4, d0 = (flat & 15) * 4;
        float4 q4 = *(const float4*)&Qg[((size_t)(qt * TQ + row) << 6) + d0];
        q4.x *= QSCALE; q4.y *= QSCALE; q4.z *= QSCALE; q4.w *= QSCALE;
        *(float4*)&Qf[row * PS_STRIDE + d0] = q4;
    }
    __syncthreads();

    uint32_t qa[8][4];
    #pragma unroll
    for (int ks = 0; ks < 8; ks++) {
        qa[ks][0] = f2tf32(Qf[(wrow + g)     * PS_STRIDE + ks * 8 + t]);
        qa[ks][1] = f2tf32(Qf[(wrow + g + 8) * PS_STRIDE + ks * 8 + t]);
        qa[ks][2] = f2tf32(Qf[(wrow + g)     * PS_STRIDE + ks * 8 + t + 4]);
        qa[ks][3] = f2tf32(Qf[(wrow + g + 8) * PS_STRIDE + ks * 8 + t + 4]);
    }

    float oacc[8][4] = {};
    float m0 = -1e30f, m1 = -1e30f, l0 = 0.f, l1 = 0.f;

    const int NT = NS / 64;
    for (int kt = 0; kt < NT; kt++) {
        __syncthreads();   // all warps done reading K/V/P smem of prev tile
        #pragma unroll
        for (int it = 0; it < 8; it++) {
            const int flat = it * 128 + tid;  // < 1024
            const int key = flat >> 4, d0 = (flat & 15) * 4;
            const size_t base = ((size_t)(kt * 64 + key) << 6) + d0;
            float4 k4 = *(const float4*)&Kg[base];
            *(uint4*)&sm[KS_OFF + key * KS_STRIDE + d0] = cvt4(k4);
            float4 v4 = *(const float4*)&Vg[base];
            *(uint4*)&sm[VS_OFF + key * VS_STRIDE + d0] = cvt4(v4);
        }
        __syncthreads();

        // S = Q K^T (log2-scaled)
        float sacc[8][4] = {};
        #pragma unroll
        for (int nt = 0; nt < 8; nt++) {
            const uint32_t* krow = &sm[KS_OFF + (nt * 8 + g) * KS_STRIDE + t];
            #pragma unroll
            for (int ks = 0; ks < 8; ks++) {
                uint32_t b[2];
                b[0] = krow[ks * 8];
                b[1] = krow[ks * 8 + 4];
                mma_tf32(sacc[nt], qa[ks], b);
            }
        }

        // Online softmax in log2 domain (rows g, g+8 of warp slab)
        float mx0 = -1e30f, mx1 = -1e30f;
        #pragma unroll
        for (int nt = 0; nt < 8; nt++) {
            mx0 = fmaxf(mx0, fmaxf(sacc[nt][0], sacc[nt][1]));
            mx1 = fmaxf(mx1, fmaxf(sacc[nt][2], sacc[nt][3]));
        }
        mx0 = fmaxf(mx0, __shfl_xor_sync(0xffffffffu, mx0, 1));
        mx0 = fmaxf(mx0, __shfl_xor_sync(0xffffffffu, mx0, 2));
        mx1 = fmaxf(mx1, __shfl_xor_sync(0xffffffffu, mx1, 1));
        mx1 = fmaxf(mx1, __shfl_xor_sync(0xffffffffu, mx1, 2));
        const float mn0 = fmaxf(m0, mx0), mn1 = fmaxf(m1, mx1);
        const float c0 = ex2(m0 - mn0), c1 = ex2(m1 - mn1);
        m0 = mn0; m1 = mn1;

        float s0 = 0.f, s1 = 0.f;
        #pragma unroll
        for (int nt = 0; nt < 8; nt++) {
            const float e0 = ex2(sacc[nt][0] - mn0);
            const float e1 = ex2(sacc[nt][1] - mn0);
            const float e2 = ex2(sacc[nt][2] - mn1);
            const float e3 = ex2(sacc[nt][3] - mn1);
            s0 += e0 + e1; s1 += e2 + e3;
            uint2 p;
            p.x = f2tf32(e0); p.y = f2tf32(e1);
            *(uint2*)&sm[PS_OFF + (wrow + g) * PS_STRIDE + nt * 8 + 2 * t] = p;
            p.x = f2tf32(e2); p.y = f2tf32(e3);
            *(uint2*)&sm[PS_OFF + (wrow + g + 8) * PS_STRIDE + nt * 8 + 2 * t] = p;
            oacc[nt][0] *= c0; oacc[nt][1] *= c0;
            oacc[nt][2] *= c1; oacc[nt][3] *= c1;
        }
        s0 += __shfl_xor_sync(0xffffffffu, s0, 1);
        s0 += __shfl_xor_sync(0xffffffffu, s0, 2);
        s1 += __shfl_xor_sync(0xffffffffu, s1, 1);
        s1 += __shfl_xor_sync(0xffffffffu, s1, 2);
        l0 = l0 * c0 + s0;
        l1 = l1 * c1 + s1;
        __syncwarp();   // this warp's P rows written before its own A-frag reads

        // O += P V
        #pragma unroll
        for (int ks = 0; ks < 8; ks++) {
            uint32_t pa[4];
            pa[0] = sm[PS_OFF + (wrow + g)     * PS_STRIDE + ks * 8 + t];
            pa[1] = sm[PS_OFF + (wrow + g + 8) * PS_STRIDE + ks * 8 + t];
            pa[2] = sm[PS_OFF + (wrow + g)     * PS_STRIDE + ks * 8 + t + 4];
            pa[3] = sm[PS_OFF + (wrow + g + 8) * PS_STRIDE + ks * 8 + t + 4];
            const uint32_t* vrow0 = &sm[VS_OFF + (ks * 8 + t)     * VS_STRIDE + g];
            const uint32_t* vrow1 = &sm[VS_OFF + (ks * 8 + t + 4) * VS_STRIDE + g];
            #pragma unroll
            for (int nt = 0; nt < 8; nt++) {
                uint32_t b[2];
                b[0] = vrow0[nt * 8];
                b[1] = vrow1[nt * 8];
                mma_tf32(oacc[nt], pa, b);
            }
        }
    }

    // Epilogue: O /= l -> ctx[s*NB+b][h*64+dk]
    const float inv0 = 1.f / l0, inv1 = 1.f / l1;
    const int h = hb >> 1, b = hb & 1;
    const int s_0 = qt * TQ + wrow + g;
    const int s_1 = s_0 + 8;
    #pragma unroll
    for (int nt = 0; nt < 8; nt++) {
        const int col = (h << 6) + nt * 8 + 2 * t;
        float2 o;
        o.x = oacc[nt][0] * inv0; o.y = oacc[nt][1] * inv0;
        *(float2*)&ctx[(size_t)(s_0 * NB + b) * DM + col] = o;
        o.x = oacc[nt][2] * inv1; o.y = oacc[nt][3] * inv1;
        *(float2*)&ctx[(size_t)(s_1 * NB + b) * DM + col] = o;
    }
}

// ---------------------------------------------------------------------------
extern "C" void kernel_launch(void* const* d_in, const int* in_sizes, int n_in,
                              void* d_out, int out_size)
{
    const float* query = (const float*)d_in[0];
    const float* key_  = (const float*)d_in[1];
    const float* value = (const float*)d_in[2];
    const float* Wq = (const float*)d_in[3];
    const float* bq = (const float*)d_in[4];
    const float* Wk = (const float*)d_in[5];
    const float* bk = (const float*)d_in[6];
    const float* Wv = (const float*)d_in[7];
    const float* bv = (const float*)d_in[8];
    const float* Wo = (const float*)d_in[9];
    const float* bo = (const float*)d_in[10];
    float* out = (float*)d_out;

    float *pQ, *pK, *pV, *pC;
    cudaGetSymbolAddress((void**)&pQ, g_Q);
    cudaGetSymbolAddress((void**)&pK, g_K);
    cudaGetSymbolAddress((void**)&pV, g_V);
    cudaGetSymbolAddress((void**)&pC, g_ctx);

    cudaFuncSetAttribute(qkv_gemm_kernel,
                         cudaFuncAttributeMaxDynamicSharedMemorySize, GSMEM_BYTES);
    cudaFuncSetAttribute(out_gemm_kernel,
                         cudaFuncAttributeMaxDynamicSharedMemorySize, GSMEM_BYTES);
    cudaFuncSetAttribute(attn_mma_kernel,
                         cudaFuncAttributeMaxDynamicSharedMemorySize, ATT_SMEM_BYTES);

    dim3 gq(DM / BN, NROWS / BM, 3);   // 8 x 32 x 3 = 768 CTAs
    qkv_gemm_kernel<<<gq, 256, GSMEM_BYTES>>>(query, key_, value, Wq, Wk, Wv,
                                              bq, bk, bv, pQ, pK, pV);

    attn_mma_kernel<<<dim3(NS / TQ, NH * NB), 128, ATT_SMEM_BYTES>>>(pQ, pK, pV, pC);

    dim3 gg(DM / BN, NROWS / BM);      // 8 x 32 = 256 CTAs
    out_gemm_kernel<<<gg, 256, GSMEM_BYTES>>>(pC, Wo, bo, out);
}

// round 8
// speedup vs baseline: 3.7866x; 1.0201x over previous
#include <cuda_runtime.h>
#include <cstdint>
#include <math.h>

#define NH 16
#define NB 2
#define NS 2048
#define DM 1024
#define DK 64
#define NROWS (NS*NB)   // 4096

// Scratch (allocation-free rule: __device__ globals)
__device__ __align__(16) float g_Q[NH*NB*NS*DK];
__device__ __align__(16) float g_K[NH*NB*NS*DK];
__device__ __align__(16) float g_V[NH*NB*NS*DK];
__device__ __align__(16) float g_ctx[(size_t)NROWS*DM];

// ---------------------------------------------------------------------------
// helpers (portable mma.sync path — compute_103 has no tcgen05)
// ---------------------------------------------------------------------------
__device__ __forceinline__ uint32_t f2tf32(float f) {
    uint32_t o;
    asm("cvt.rna.tf32.f32 %0, %1;" : "=r"(o) : "f"(f));
    return o;
}
__device__ __forceinline__ float ex2(float x) {
    float r;
    asm("ex2.approx.ftz.f32 %0, %1;" : "=f"(r) : "f"(x));
    return r;
}
__device__ __forceinline__ void mma_tf32(float c[4], const uint32_t a[4], const uint32_t b[2]) {
    asm volatile(
        "mma.sync.aligned.m16n8k8.row.col.f32.tf32.tf32.f32 "
        "{%0,%1,%2,%3}, {%4,%5,%6,%7}, {%8,%9}, {%0,%1,%2,%3};"
        : "+f"(c[0]), "+f"(c[1]), "+f"(c[2]), "+f"(c[3])
        : "r"(a[0]), "r"(a[1]), "r"(a[2]), "r"(a[3]), "r"(b[0]), "r"(b[1]));
}
__device__ __forceinline__ uint32_t smem_u32(const void* p) {
    uint32_t a;
    asm("{ .reg .u64 t; cvta.to.shared.u64 t, %1; cvt.u32.u64 %0, t; }" : "=r"(a) : "l"(p));
    return a;
}
__device__ __forceinline__ void cp_async16(uint32_t dst, const void* src) {
    asm volatile("cp.async.cg.shared.global [%0], [%1], 16;" :: "r"(dst), "l"(src));
}
__device__ __forceinline__ void cp_commit() { asm volatile("cp.async.commit_group;" ::: "memory"); }
template<int N> __device__ __forceinline__ void cp_wait() {
    asm volatile("cp.async.wait_group %0;" :: "n"(N) : "memory");
}

// ---------------------------------------------------------------------------
// tf32 mma.sync NT GEMM (unchanged from R6): out = X[.,DM] @ W[DM,DM]^T + bias
// ---------------------------------------------------------------------------
#define BM 128
#define BN 128
#define BK 16
#define LDS_STRIDE 20
#define STG_U32 (BM * LDS_STRIDE)
#define STAGES 4
#define GSMEM_BYTES (STAGES * STG_U32 * 4 * 2)   // 81920

template<int MODE>
__device__ __forceinline__ void gemm_body(const float* __restrict__ X,
                                          const float* __restrict__ W,
                                          const float* __restrict__ bias,
                                          float* __restrict__ out,
                                          int rT, int cT)
{
    extern __shared__ uint32_t dyn[];
    float* As = (float*)dyn;
    float* Bs = (float*)(dyn + STAGES * STG_U32);

    const int tid = threadIdx.x;
    const int wid = tid >> 5, lid = tid & 31;
    const int wm  = wid >> 2;
    const int wn  = wid & 3;
    const int g   = lid >> 2;
    const int t   = lid & 3;

    const int lr0 = (tid * 4) >> 4;
    const int lr1 = lr0 + 64;
    const int lc  = (tid * 4) & 15;

    const uint32_t aB = smem_u32(As), bB = smem_u32(Bs);
    const uint32_t off0 = (uint32_t)(lr0 * LDS_STRIDE + lc) * 4;
    const uint32_t off1 = (uint32_t)(lr1 * LDS_STRIDE + lc) * 4;
    const uint32_t SSB  = STG_U32 * 4;
    const float* xr0 = &X[(size_t)(rT + lr0) * DM + lc];
    const float* xr1 = &X[(size_t)(rT + lr1) * DM + lc];
    const float* wr0 = &W[(size_t)(cT + lr0) * DM + lc];
    const float* wr1 = &W[(size_t)(cT + lr1) * DM + lc];

    #pragma unroll
    for (int s = 0; s < STAGES - 1; s++) {
        const int kk = s << 4;
        cp_async16(aB + s * SSB + off0, xr0 + kk);
        cp_async16(aB + s * SSB + off1, xr1 + kk);
        cp_async16(bB + s * SSB + off0, wr0 + kk);
        cp_async16(bB + s * SSB + off1, wr1 + kk);
        cp_commit();
    }

    float acc[4][4][4] = {};
    const int NCHUNK = DM / BK;   // 64
    for (int c = 0; c < NCHUNK; c++) {
        cp_wait<STAGES - 2>();
        __syncthreads();

        if (c + STAGES - 1 < NCHUNK) {
            const int s = (c + STAGES - 1) & (STAGES - 1);
            const int kk = (c + STAGES - 1) << 4;
            cp_async16(aB + s * SSB + off0, xr0 + kk);
            cp_async16(aB + s * SSB + off1, xr1 + kk);
            cp_async16(bB + s * SSB + off0, wr0 + kk);
            cp_async16(bB + s * SSB + off1, wr1 + kk);
        }
        cp_commit();

        const float* Ap = As + (c & (STAGES - 1)) * STG_U32;
        const float* Bp = Bs + (c & (STAGES - 1)) * STG_U32;

        #pragma unroll
        for (int ks = 0; ks < BK; ks += 8) {
            uint32_t a[4][4], b[4][2];
            #pragma unroll
            for (int mt = 0; mt < 4; mt++) {
                const int row = wm * 64 + mt * 16 + g;
                a[mt][0] = f2tf32(Ap[row * LDS_STRIDE + ks + t]);
                a[mt][1] = f2tf32(Ap[(row + 8) * LDS_STRIDE + ks + t]);
                a[mt][2] = f2tf32(Ap[row * LDS_STRIDE + ks + t + 4]);
                a[mt][3] = f2tf32(Ap[(row + 8) * LDS_STRIDE + ks + t + 4]);
            }
            #pragma unroll
            for (int nt = 0; nt < 4; nt++) {
                const int col = wn * 32 + nt * 8 + g;
                b[nt][0] = f2tf32(Bp[col * LDS_STRIDE + ks + t]);
                b[nt][1] = f2tf32(Bp[col * LDS_STRIDE + ks + t + 4]);
            }
            #pragma unroll
            for (int mt = 0; mt < 4; mt++)
                #pragma unroll
                for (int nt = 0; nt < 4; nt++)
                    mma_tf32(acc[mt][nt], a[mt], b[nt]);
        }
    }

    #pragma unroll
    for (int mt = 0; mt < 4; mt++) {
        #pragma unroll
        for (int nt = 0; nt < 4; nt++) {
            const int col = cT + wn * 32 + nt * 8 + 2 * t;
            const float bx = bias[col], by = bias[col + 1];
            #pragma unroll
            for (int half = 0; half < 2; half++) {
                const int row = rT + wm * 64 + mt * 16 + g + half * 8;
                float2 o;
                o.x = acc[mt][nt][half * 2 + 0] + bx;
                o.y = acc[mt][nt][half * 2 + 1] + by;
                if (MODE == 0) {
                    const int h = col >> 6, dk = col & 63;
                    const int s = row >> 1, b = row & 1;
                    *(float2*)&out[(((size_t)(h * NB + b) * NS + s) << 6) + dk] = o;
                } else {
                    *(float2*)&out[(size_t)row * DM + col] = o;
                }
            }
        }
    }
}

__global__ __launch_bounds__(256, 2)
void qkv_gemm_kernel(const float* __restrict__ q, const float* __restrict__ k,
                     const float* __restrict__ v,
                     const float* __restrict__ Wq, const float* __restrict__ Wk,
                     const float* __restrict__ Wv,
                     const float* __restrict__ bq, const float* __restrict__ bk,
                     const float* __restrict__ bv,
                     float* oq, float* ok, float* ov)
{
    const float *X, *W, *B;
    float* O;
    if (blockIdx.z == 0)      { X = q; W = Wq; B = bq; O = oq; }
    else if (blockIdx.z == 1) { X = k; W = Wk; B = bk; O = ok; }
    else                      { X = v; W = Wv; B = bv; O = ov; }
    gemm_body<0>(X, W, B, O, blockIdx.y << 7, blockIdx.x << 7);
}

__global__ __launch_bounds__(256, 2)
void out_gemm_kernel(const float* __restrict__ X, const float* __restrict__ W,
                     const float* __restrict__ B, float* O)
{
    gemm_body<1>(X, W, B, O, blockIdx.y << 7, blockIdx.x << 7);
}

// ---------------------------------------------------------------------------
// Flash attention, tf32 mma.sync + cp.async double-buffered K/V.
// CTA = 128 q-rows of one (h,b); 256 threads / 8 warps (16 rows each).
// K/V land in smem as RAW fp32 via cp.async (2 stages) and are consumed
// directly by mma.sync as truncated tf32 (HW reads bits[31:13]). Q and P go
// through cvt.rna. One wait+syncthreads per tile; tile kt+1's loads fly under
// tile kt's MMA work. Strides: K/P 68 (bank=4g+t), V 72 (bank=8t+g).
// ---------------------------------------------------------------------------
#define TQ 128
#define KS_STRIDE 68
#define VS_STRIDE 72
#define PS_STRIDE 68
#define ATT_STG (64 * KS_STRIDE + 64 * VS_STRIDE)   // 8960 u32 per stage
#define PS_OFF (2 * ATT_STG)                        // 17920
#define ATT_SMEM_U32 (PS_OFF + TQ * PS_STRIDE)      // 26624
#define ATT_SMEM_BYTES (ATT_SMEM_U32 * 4)           // 106496

#define QSCALE (0.125f * 1.4426950408889634f)

__global__ __launch_bounds__(256, 2)
void attn_mma_kernel(const float* __restrict__ Qg_,
                     const float* __restrict__ Kg_,
                     const float* __restrict__ Vg_,
                     float* __restrict__ ctx)
{
    extern __shared__ uint32_t sm[];
    const uint32_t smb = smem_u32(sm);

    const int tid = threadIdx.x;
    const int wid = tid >> 5, lid = tid & 31;
    const int g   = lid >> 2, t = lid & 3;
    const int wrow = wid * 16;
    const int qt = blockIdx.x;
    const int hb = blockIdx.y;

    const float* Qg = Qg_ + ((size_t)hb * NS << 6);
    const float* Kg = Kg_ + ((size_t)hb * NS << 6);
    const float* Vg = Vg_ + ((size_t)hb * NS << 6);

    // Per-thread K/V async-copy coords (fixed across tiles): 4 float4 each
    const int akey = tid >> 4;            // 0..15 base key (4 rounds of +16)
    const int ad0  = (tid & 15) * 4;      // d offset

    // Prologue: stage 0 <- tile 0
    {
        #pragma unroll
        for (int it = 0; it < 4; it++) {
            const int key = akey + it * 16;
            const size_t src = ((size_t)key << 6) + ad0;
            cp_async16(smb + (uint32_t)(key * KS_STRIDE + ad0) * 4, &Kg[src]);
            cp_async16(smb + (uint32_t)(64 * KS_STRIDE + key * VS_STRIDE + ad0) * 4, &Vg[src]);
        }
        cp_commit();
    }

    // Stage Q (pre-scaled into log2 domain) into P area, build A frags
    float* Qf = (float*)(sm + PS_OFF);
    #pragma unroll
    for (int it = 0; it < 8; it++) {
        const int flat = it * 256 + tid;      // < 2048
        const int row = flat >> 4, d0 = (flat & 15) * 4;
        float4 q4 = *(const float4*)&Qg[((size_t)(qt * TQ + row) << 6) + d0];
        q4.x *= QSCALE; q4.y *= QSCALE; q4.z *= QSCALE; q4.w *= QSCALE;
        *(float4*)&Qf[row * PS_STRIDE + d0] = q4;
    }
    __syncthreads();

    uint32_t qa[8][4];
    #pragma unroll
    for (int ks = 0; ks < 8; ks++) {
        qa[ks][0] = f2tf32(Qf[(wrow + g)     * PS_STRIDE + ks * 8 + t]);
        qa[ks][1] = f2tf32(Qf[(wrow + g + 8) * PS_STRIDE + ks * 8 + t]);
        qa[ks][2] = f2tf32(Qf[(wrow + g)     * PS_STRIDE + ks * 8 + t + 4]);
        qa[ks][3] = f2tf32(Qf[(wrow + g + 8) * PS_STRIDE + ks * 8 + t + 4]);
    }

    float oacc[8][4] = {};
    float m0 = -1e30f, m1 = -1e30f, l0 = 0.f, l1 = 0.f;

    const int NT = NS / 64;
    for (int kt = 0; kt < NT; kt++) {
        cp_wait<0>();
        __syncthreads();   // tile kt landed; all warps past PV reads of kt-1

        // Issue tile kt+1 into the other stage (overlaps with compute below)
        if (kt + 1 < NT) {
            const uint32_t sb = ((kt + 1) & 1) * (ATT_STG * 4);
            #pragma unroll
            for (int it = 0; it < 4; it++) {
                const int key = akey + it * 16;
                const size_t src = ((size_t)((kt + 1) * 64 + key) << 6) + ad0;
                cp_async16(smb + sb + (uint32_t)(key * KS_STRIDE + ad0) * 4, &Kg[src]);
                cp_async16(smb + sb + (uint32_t)(64 * KS_STRIDE + key * VS_STRIDE + ad0) * 4, &Vg[src]);
            }
        }
        cp_commit();

        const uint32_t* Kb = sm + (kt & 1) * ATT_STG;
        const uint32_t* Vb = Kb + 64 * KS_STRIDE;

        // S = Q K^T (log2-scaled); K consumed as truncated tf32
        float sacc[8][4] = {};
        #pragma unroll
        for (int nt = 0; nt < 8; nt++) {
            const uint32_t* krow = &Kb[(nt * 8 + g) * KS_STRIDE + t];
            #pragma unroll
            for (int ks = 0; ks < 8; ks++) {
                uint32_t b[2];
                b[0] = krow[ks * 8];
                b[1] = krow[ks * 8 + 4];
                mma_tf32(sacc[nt], qa[ks], b);
            }
        }

        // Online softmax in log2 domain (rows g, g+8 of warp slab)
        float mx0 = -1e30f, mx1 = -1e30f;
        #pragma unroll
        for (int nt = 0; nt < 8; nt++) {
            mx0 = fmaxf(mx0, fmaxf(sacc[nt][0], sacc[nt][1]));
            mx1 = fmaxf(mx1, fmaxf(sacc[nt][2], sacc[nt][3]));
        }
        mx0 = fmaxf(mx0, __shfl_xor_sync(0xffffffffu, mx0, 1));
        mx0 = fmaxf(mx0, __shfl_xor_sync(0xffffffffu, mx0, 2));
        mx1 = fmaxf(mx1, __shfl_xor_sync(0xffffffffu, mx1, 1));
        mx1 = fmaxf(mx1, __shfl_xor_sync(0xffffffffu, mx1, 2));
        const float mn0 = fmaxf(m0, mx0), mn1 = fmaxf(m1, mx1);
        const float c0 = ex2(m0 - mn0), c1 = ex2(m1 - mn1);
        m0 = mn0; m1 = mn1;

        float s0 = 0.f, s1 = 0.f;
        #pragma unroll
        for (int nt = 0; nt < 8; nt++) {
            const float e0 = ex2(sacc[nt][0] - mn0);
            const float e1 = ex2(sacc[nt][1] - mn0);
            const float e2 = ex2(sacc[nt][2] - mn1);
            const float e3 = ex2(sacc[nt][3] - mn1);
            s0 += e0 + e1; s1 += e2 + e3;
            uint2 p;
            p.x = f2tf32(e0); p.y = f2tf32(e1);
            *(uint2*)&sm[PS_OFF + (wrow + g) * PS_STRIDE + nt * 8 + 2 * t] = p;
            p.x = f2tf32(e2); p.y = f2tf32(e3);
            *(uint2*)&sm[PS_OFF + (wrow + g + 8) * PS_STRIDE + nt * 8 + 2 * t] = p;
            oacc[nt][0] *= c0; oacc[nt][1] *= c0;
            oacc[nt][2] *= c1; oacc[nt][3] *= c1;
        }
        s0 += __shfl_xor_sync(0xffffffffu, s0, 1);
        s0 += __shfl_xor_sync(0xffffffffu, s0, 2);
        s1 += __shfl_xor_sync(0xffffffffu, s1, 1);
        s1 += __shfl_xor_sync(0xffffffffu, s1, 2);
        l0 = l0 * c0 + s0;
        l1 = l1 * c1 + s1;
        __syncwarp();   // this warp's P rows written before its own A-frag reads

        // O += P V; V consumed as truncated tf32
        #pragma unroll
        for (int ks = 0; ks < 8; ks++) {
            uint32_t pa[4];
            pa[0] = sm[PS_OFF + (wrow + g)     * PS_STRIDE + ks * 8 + t];
            pa[1] = sm[PS_OFF + (wrow + g + 8) * PS_STRIDE + ks * 8 + t];
            pa[2] = sm[PS_OFF + (wrow + g)     * PS_STRIDE + ks * 8 + t + 4];
            pa[3] = sm[PS_OFF + (wrow + g + 8) * PS_STRIDE + ks * 8 + t + 4];
            const uint32_t* vrow0 = &Vb[(ks * 8 + t)     * VS_STRIDE + g];
            const uint32_t* vrow1 = &Vb[(ks * 8 + t + 4) * VS_STRIDE + g];
            #pragma unroll
            for (int nt = 0; nt < 8; nt++) {
                uint32_t b[2];
                b[0] = vrow0[nt * 8];
                b[1] = vrow1[nt * 8];
                mma_tf32(oacc[nt], pa, b);
            }
        }
    }

    // Epilogue: O /= l -> ctx[s*NB+b][h*64+dk]
    const float inv0 = 1.f / l0, inv1 = 1.f / l1;
    const int h = hb >> 1, b = hb & 1;
    const int s_0 = qt * TQ + wrow + g;
    const int s_1 = s_0 + 8;
    #pragma unroll
    for (int nt = 0; nt < 8; nt++) {
        const int col = (h << 6) + nt * 8 + 2 * t;
        float2 o;
        o.x = oacc[nt][0] * inv0; o.y = oacc[nt][1] * inv0;
        *(float2*)&ctx[(size_t)(s_0 * NB + b) * DM + col] = o;
        o.x = oacc[nt][2] * inv1; o.y = oacc[nt][3] * inv1;
        *(float2*)&ctx[(size_t)(s_1 * NB + b) * DM + col] = o;
    }
}

// ---------------------------------------------------------------------------
extern "C" void kernel_launch(void* const* d_in, const int* in_sizes, int n_in,
                              void* d_out, int out_size)
{
    const float* query = (const float*)d_in[0];
    const float* key_  = (const float*)d_in[1];
    const float* value = (const float*)d_in[2];
    const float* Wq = (const float*)d_in[3];
    const float* bq = (const float*)d_in[4];
    const float* Wk = (const float*)d_in[5];
    const float* bk = (const float*)d_in[6];
    const float* Wv = (const float*)d_in[7];
    const float* bv = (const float*)d_in[8];
    const float* Wo = (const float*)d_in[9];
    const float* bo = (const float*)d_in[10];
    float* out = (float*)d_out;

    float *pQ, *pK, *pV, *pC;
    cudaGetSymbolAddress((void**)&pQ, g_Q);
    cudaGetSymbolAddress((void**)&pK, g_K);
    cudaGetSymbolAddress((void**)&pV, g_V);
    cudaGetSymbolAddress((void**)&pC, g_ctx);

    cudaFuncSetAttribute(qkv_gemm_kernel,
                         cudaFuncAttributeMaxDynamicSharedMemorySize, GSMEM_BYTES);
    cudaFuncSetAttribute(out_gemm_kernel,
                         cudaFuncAttributeMaxDynamicSharedMemorySize, GSMEM_BYTES);
    cudaFuncSetAttribute(attn_mma_kernel,
                         cudaFuncAttributeMaxDynamicSharedMemorySize, ATT_SMEM_BYTES);

    dim3 gq(DM / BN, NROWS / BM, 3);   // 8 x 32 x 3 = 768 CTAs
    qkv_gemm_kernel<<<gq, 256, GSMEM_BYTES>>>(query, key_, value, Wq, Wk, Wv,
                                              bq, bk, bv, pQ, pK, pV);

    attn_mma_kernel<<<dim3(NS / TQ, NH * NB), 256, ATT_SMEM_BYTES>>>(pQ, pK, pV, pC);

    dim3 gg(DM / BN, NROWS / BM);      // 8 x 32 = 256 CTAs
    out_gemm_kernel<<<gg, 256, GSMEM_BYTES>>>(pC, Wo, bo, out);
}